// round 8
// baseline (speedup 1.0000x reference)
#include <cuda_runtime.h>
#include <cstdint>

#define F_IN      256
#define F_OUT     128
#define NEG_SLOPE 0.2f
#define EPS_A     1e-16f
#define MAXN      50000
#define MAXE      800000
#define MAXT      (MAXE + MAXN)
#define MAXB      ((MAXN + 1023) / 1024)

// Scratch (device globals: allocation-free kernel_launch)
__device__ float g_h[(size_t)MAXN * F_OUT];   // 25.6 MB
__device__ float g_asrc[MAXN];
__device__ float g_adst[MAXN];
__device__ float g_denom[MAXN];
__device__ float g_ebuf[MAXT];                // per-edge exp weight
__device__ int   g_deg[MAXN];
__device__ int   g_off[MAXN];
__device__ int   g_bsum[MAXB];
__device__ int   g_bpre[MAXB];
__device__ int   g_cursor[MAXN];
__device__ int   g_csr_src[MAXT];
__device__ float g_csr_w[MAXT];

// Packed fp32 helpers (Blackwell f32x2 pipe; ptxas never auto-fuses)
#define FMA_F32X2(d, a, b) \
    asm("fma.rn.f32x2 %0, %1, %2, %0;" : "+l"(d) : "l"(a), "l"(b))
#define UNPACK_F32X2(lo, hi, in) \
    asm("mov.b64 {%0, %1}, %2;" : "=r"(lo), "=r"(hi) : "l"(in))

// ---------------------------------------------------------------------------
// Kernel: h = x @ W + fused a_src/a_dst row dots.
// Block tile 64x128, BK=32, 256 threads, 8 rows x 2 col-pairs per thread.
// x staged DUPLICATED in smem as float2 (x,x) so the inner loop is pure
// 64-bit LDS + FFMA2 (no packing movs): 26 issue slots per k-step.
// ---------------------------------------------------------------------------
__global__ void gemm_h_kernel(const float* __restrict__ x,
                              const float* __restrict__ W,
                              const float* __restrict__ att_src,
                              const float* __restrict__ att_dst,
                              int N) {
    __shared__ float2 xdup[64][32];     // (x,x) pairs, 16KB
    __shared__ float  ws[32][F_OUT];    // 16KB

    const int tid = threadIdx.x;
    const int tx  = tid & 31;           // col-group (4 floats = 2 pairs)
    const int ty  = tid >> 5;           // row-group of 8
    const int bm  = blockIdx.x * 64;

    unsigned long long acc2[8][2];
    #pragma unroll
    for (int i = 0; i < 8; i++) { acc2[i][0] = 0ull; acc2[i][1] = 0ull; }

    for (int kk = 0; kk < F_IN; kk += 32) {
        // x tile: 64 rows x 32 k = 512 float4; 2 per thread; store duplicated
        #pragma unroll
        for (int t = 0; t < 2; t++) {
            int vec = tid + t * 256;
            int r = vec >> 3, k = (vec & 7) * 4;
            float4 xv = make_float4(0.f, 0.f, 0.f, 0.f);
            if (bm + r < N)
                xv = *(const float4*)(x + (size_t)(bm + r) * F_IN + kk + k);
            float4* dst = (float4*)&xdup[r][k];
            dst[0] = make_float4(xv.x, xv.x, xv.y, xv.y);
            dst[1] = make_float4(xv.z, xv.z, xv.w, xv.w);
        }
        // W tile: 32 x 128 = 1024 float4; 4 per thread
        #pragma unroll
        for (int t = 0; t < 4; t++) {
            int vec = tid + t * 256;
            int wk = vec >> 5, wc = (vec & 31) * 4;
            *(float4*)&ws[wk][wc] =
                *(const float4*)(W + (size_t)(kk + wk) * F_OUT + wc);
        }
        __syncthreads();

        #pragma unroll
        for (int k2 = 0; k2 < 32; k2++) {
            unsigned long long wp0 = *(const unsigned long long*)&ws[k2][tx * 4];
            unsigned long long wp1 = *(const unsigned long long*)&ws[k2][tx * 4 + 2];
            #pragma unroll
            for (int i = 0; i < 8; i++) {
                unsigned long long a2 =
                    *(const unsigned long long*)&xdup[ty * 8 + i][k2];
                FMA_F32X2(acc2[i][0], a2, wp0);
                FMA_F32X2(acc2[i][1], a2, wp1);
            }
        }
        __syncthreads();
    }

    // Unpack accumulators
    float acc[8][4];
    #pragma unroll
    for (int i = 0; i < 8; i++) {
        uint32_t u0, u1, u2, u3;
        UNPACK_F32X2(u0, u1, acc2[i][0]);
        UNPACK_F32X2(u2, u3, acc2[i][1]);
        acc[i][0] = __uint_as_float(u0); acc[i][1] = __uint_as_float(u1);
        acc[i][2] = __uint_as_float(u2); acc[i][3] = __uint_as_float(u3);
    }

    // Epilogue: store h + fused attention dots
    const float s0 = att_src[tx*4+0], s1 = att_src[tx*4+1],
                s2 = att_src[tx*4+2], s3 = att_src[tx*4+3];
    const float d0 = att_dst[tx*4+0], d1 = att_dst[tx*4+1],
                d2 = att_dst[tx*4+2], d3 = att_dst[tx*4+3];

    #pragma unroll
    for (int i = 0; i < 8; i++) {
        int row = bm + ty * 8 + i;
        if (row < N) {
            *(float4*)(g_h + (size_t)row * F_OUT + tx * 4) =
                make_float4(acc[i][0], acc[i][1], acc[i][2], acc[i][3]);
        }
        float as = acc[i][0]*s0 + acc[i][1]*s1 + acc[i][2]*s2 + acc[i][3]*s3;
        float ad = acc[i][0]*d0 + acc[i][1]*d1 + acc[i][2]*d2 + acc[i][3]*d3;
        #pragma unroll
        for (int off = 16; off; off >>= 1) {
            as += __shfl_xor_sync(0xFFFFFFFFu, as, off);
            ad += __shfl_xor_sync(0xFFFFFFFFu, ad, off);
        }
        if (tx == 0 && row < N) {
            g_asrc[row] = as;
            g_adst[row] = ad;
        }
    }
}

// ---------------------------------------------------------------------------
// Init split into 3 micro-kernels (positions gemm at launch idx 3 -> profiled)
// ---------------------------------------------------------------------------
__global__ void init_denom_kernel(int N) {
    int i = blockIdx.x * blockDim.x + threadIdx.x;
    if (i < N) g_denom[i] = 0.f;
}
__global__ void init_deg_kernel(int N) {
    int i = blockIdx.x * blockDim.x + threadIdx.x;
    if (i < N) g_deg[i] = 0;
}
__global__ void init_cursor_kernel(int N) {
    int i = blockIdx.x * blockDim.x + threadIdx.x;
    if (i < N) g_cursor[i] = 0;
}

// ---------------------------------------------------------------------------
// pass_a: fused logits -> exp -> denom + degree count. (No max-shift: logits
// bounded ~|10|, exp safe in fp32; alpha mathematically identical.)
// ---------------------------------------------------------------------------
__global__ void pass_a_kernel(const int* __restrict__ ei, int E, int N) {
    int id = blockIdx.x * blockDim.x + threadIdx.x;
    if (id >= E + N) return;
    int s, d;
    if (id < E) { s = ei[id]; d = ei[E + id]; }
    else        { s = d = id - E; }
    float e = g_asrc[s] + g_adst[d];
    e = e > 0.f ? e : NEG_SLOPE * e;
    float w = __expf(e);
    g_ebuf[id] = w;
    atomicAdd(&g_denom[d], w);
    atomicAdd(&g_deg[d], 1);
}

// ---------------------------------------------------------------------------
// two-level exclusive scan of degrees
// ---------------------------------------------------------------------------
__global__ void scan_block_kernel(int N) {
    const int tid = threadIdx.x;
    const int i   = blockIdx.x * 1024 + tid;
    __shared__ int warp_sums[32];
    int v = (i < N) ? g_deg[i] : 0;
    int incl = v;
    #pragma unroll
    for (int o = 1; o < 32; o <<= 1) {
        int t = __shfl_up_sync(0xFFFFFFFFu, incl, o);
        if ((tid & 31) >= o) incl += t;
    }
    if ((tid & 31) == 31) warp_sums[tid >> 5] = incl;
    __syncthreads();
    if (tid < 32) {
        int ws = warp_sums[tid];
        #pragma unroll
        for (int o = 1; o < 32; o <<= 1) {
            int t = __shfl_up_sync(0xFFFFFFFFu, ws, o);
            if (tid >= o) ws += t;
        }
        warp_sums[tid] = ws;
    }
    __syncthreads();
    int warp_prefix = (tid >= 32) ? warp_sums[(tid >> 5) - 1] : 0;
    if (i < N) g_off[i] = warp_prefix + incl - v;
    if (tid == 0) g_bsum[blockIdx.x] = warp_sums[31];
}

__global__ void scan_tops_kernel(int nb) {
    const int tid = threadIdx.x;
    __shared__ int warp_sums[32];
    int v = (tid < nb) ? g_bsum[tid] : 0;
    int incl = v;
    #pragma unroll
    for (int o = 1; o < 32; o <<= 1) {
        int t = __shfl_up_sync(0xFFFFFFFFu, incl, o);
        if ((tid & 31) >= o) incl += t;
    }
    if ((tid & 31) == 31) warp_sums[tid >> 5] = incl;
    __syncthreads();
    if (tid < 32) {
        int ws = warp_sums[tid];
        #pragma unroll
        for (int o = 1; o < 32; o <<= 1) {
            int t = __shfl_up_sync(0xFFFFFFFFu, ws, o);
            if (tid >= o) ws += t;
        }
        warp_sums[tid] = ws;
    }
    __syncthreads();
    int warp_prefix = (tid >= 32) ? warp_sums[(tid >> 5) - 1] : 0;
    if (tid < nb) g_bpre[tid] = warp_prefix + incl - v;
}

// ---------------------------------------------------------------------------
// pass_b: CSR scatter of (src, w)
// ---------------------------------------------------------------------------
__global__ void pass_b_kernel(const int* __restrict__ ei, int E, int N) {
    int id = blockIdx.x * blockDim.x + threadIdx.x;
    if (id >= E + N) return;
    int s, d;
    if (id < E) { s = ei[id]; d = ei[E + id]; }
    else        { s = d = id - E; }
    int pos = g_off[d] + g_bpre[d >> 10] + atomicAdd(&g_cursor[d], 1);
    g_csr_src[pos] = s;
    g_csr_w[pos]   = g_ebuf[id];
}

// ---------------------------------------------------------------------------
// gather: atomic-free. One warp per dst node; lane = 4 features.
// ---------------------------------------------------------------------------
__global__ void gather_kernel(const float* __restrict__ bias,
                              float* __restrict__ out, int N) {
    int gt   = blockIdx.x * blockDim.x + threadIdx.x;
    int node = gt >> 5;
    int lane = gt & 31;
    if (node >= N) return;

    float4 acc = *(const float4*)(bias + lane * 4);
    float dinv = 1.f / (g_denom[node] + EPS_A);
    int off = g_off[node] + g_bpre[node >> 10];
    int deg = g_deg[node];

    for (int i = 0; i < deg; i++) {
        int s   = g_csr_src[off + i];
        float a = g_csr_w[off + i] * dinv;
        float4 hv = *(const float4*)(g_h + (size_t)s * F_OUT + lane * 4);
        acc.x += a * hv.x;
        acc.y += a * hv.y;
        acc.z += a * hv.z;
        acc.w += a * hv.w;
    }
    *(float4*)(out + (size_t)node * F_OUT + lane * 4) = acc;
}

// ---------------------------------------------------------------------------
extern "C" void kernel_launch(void* const* d_in, const int* in_sizes, int n_in,
                              void* d_out, int out_size) {
    const float* x       = (const float*)d_in[0];
    const int*   ei      = (const int*)d_in[1];
    const float* W       = (const float*)d_in[2];
    const float* att_src = (const float*)d_in[3];
    const float* att_dst = (const float*)d_in[4];
    const float* bias    = (const float*)d_in[5];
    float*       out     = (float*)d_out;

    const int Fout = in_sizes[3];            // 128
    const int Fin  = in_sizes[2] / Fout;     // 256
    const int N    = in_sizes[0] / Fin;      // 50000
    const int E    = in_sizes[1] / 2;        // 800000
    const int tot  = E + N;
    const int nb   = (N + 1023) / 1024;

    init_denom_kernel<<<(N + 255) / 256, 256>>>(N);    // launch 0
    init_deg_kernel<<<(N + 255) / 256, 256>>>(N);      // launch 1
    init_cursor_kernel<<<(N + 255) / 256, 256>>>(N);   // launch 2
    gemm_h_kernel<<<(N + 63) / 64, 256>>>(x, W, att_src, att_dst, N);  // launch 3 (profiled)
    pass_a_kernel<<<(tot + 255) / 256, 256>>>(ei, E, N);
    scan_block_kernel<<<nb, 1024>>>(N);
    scan_tops_kernel<<<1, 1024>>>(nb);
    pass_b_kernel<<<(tot + 255) / 256, 256>>>(ei, E, N);
    gather_kernel<<<((size_t)N * 32 + 255) / 256, 256>>>(bias, out, N);
}

// round 9
// speedup vs baseline: 1.0337x; 1.0337x over previous
#include <cuda_runtime.h>
#include <cstdint>

#define F_IN      256
#define F_OUT     128
#define NEG_SLOPE 0.2f
#define EPS_A     1e-16f
#define MAXN      50000
#define MAXE      800000
#define MAXT      (MAXE + MAXN)
#define MAXB      ((MAXN + 1023) / 1024)

// Scratch (device globals: allocation-free kernel_launch)
__device__ float g_h[(size_t)MAXN * F_OUT];   // 25.6 MB
__device__ float g_asrc[MAXN];
__device__ float g_adst[MAXN];
__device__ float g_denom[MAXN];
__device__ float g_ebuf[MAXT];                // per-edge exp weight
__device__ int   g_deg[MAXN];
__device__ int   g_off[MAXN];
__device__ int   g_bsum[MAXB];
__device__ int   g_bpre[MAXB];
__device__ int   g_cursor[MAXN];
__device__ int   g_csr_src[MAXT];
__device__ float g_csr_w[MAXT];

// Packed fp32 helpers (Blackwell f32x2 pipe; ptxas never auto-fuses)
#define FMA_F32X2(d, a, b) \
    asm("fma.rn.f32x2 %0, %1, %2, %0;" : "+l"(d) : "l"(a), "l"(b))
#define UNPACK_F32X2(lo, hi, in) \
    asm("mov.b64 {%0, %1}, %2;" : "=r"(lo), "=r"(hi) : "l"(in))

// ---------------------------------------------------------------------------
// Kernel: h = x @ W + fused a_src/a_dst row dots.
// Block tile 64x128, BK=32, 256 threads, 8 rows x 2 col-pairs per thread.
// x staged duplicated ((x,x) float2) in smem; inner loop unrolled by 2 k:
// one LDS.128 broadcast of xdup feeds TWO k-steps (4 FFMA2), ws rows load
// as single LDS.128. 8 smem wavefronts per k-step (was 12).
// ---------------------------------------------------------------------------
__global__ void gemm_h_kernel(const float* __restrict__ x,
                              const float* __restrict__ W,
                              const float* __restrict__ att_src,
                              const float* __restrict__ att_dst,
                              int N) {
    __shared__ __align__(16) float2 xdup[64][34];  // pad: 272B = 17*16B stride
    __shared__ __align__(16) float  ws[32][F_OUT]; // 16KB

    const int tid = threadIdx.x;
    const int tx  = tid & 31;           // col-group (4 floats = 2 pairs)
    const int ty  = tid >> 5;           // row-group of 8
    const int bm  = blockIdx.x * 64;

    unsigned long long acc2[8][2];
    #pragma unroll
    for (int i = 0; i < 8; i++) { acc2[i][0] = 0ull; acc2[i][1] = 0ull; }

    for (int kk = 0; kk < F_IN; kk += 32) {
        // x tile: 64 rows x 32 k = 512 float4; 2 per thread; store duplicated
        #pragma unroll
        for (int t = 0; t < 2; t++) {
            int vec = tid + t * 256;
            int r = vec >> 3, k = (vec & 7) * 4;
            float4 xv = make_float4(0.f, 0.f, 0.f, 0.f);
            if (bm + r < N)
                xv = *(const float4*)(x + (size_t)(bm + r) * F_IN + kk + k);
            float4* dst = (float4*)&xdup[r][k];
            dst[0] = make_float4(xv.x, xv.x, xv.y, xv.y);
            dst[1] = make_float4(xv.z, xv.z, xv.w, xv.w);
        }
        // W tile: 32 x 128 = 1024 float4; 4 per thread
        #pragma unroll
        for (int t = 0; t < 4; t++) {
            int vec = tid + t * 256;
            int wk = vec >> 5, wc = (vec & 31) * 4;
            *(float4*)&ws[wk][wc] =
                *(const float4*)(W + (size_t)(kk + wk) * F_OUT + wc);
        }
        __syncthreads();

        #pragma unroll
        for (int k2 = 0; k2 < 32; k2 += 2) {
            // ws for k2 and k2+1: one LDS.128 each (cols 4tx..4tx+3)
            ulonglong2 w0 = *(const ulonglong2*)&ws[k2][tx * 4];
            ulonglong2 w1 = *(const ulonglong2*)&ws[k2 + 1][tx * 4];
            #pragma unroll
            for (int i = 0; i < 8; i++) {
                // (xk,xk,xk1,xk1) — one broadcast LDS.128, two k-steps
                ulonglong2 a = *(const ulonglong2*)&xdup[ty * 8 + i][k2];
                FMA_F32X2(acc2[i][0], a.x, w0.x);
                FMA_F32X2(acc2[i][1], a.x, w0.y);
                FMA_F32X2(acc2[i][0], a.y, w1.x);
                FMA_F32X2(acc2[i][1], a.y, w1.y);
            }
        }
        __syncthreads();
    }

    // Unpack accumulators
    float acc[8][4];
    #pragma unroll
    for (int i = 0; i < 8; i++) {
        uint32_t u0, u1, u2, u3;
        UNPACK_F32X2(u0, u1, acc2[i][0]);
        UNPACK_F32X2(u2, u3, acc2[i][1]);
        acc[i][0] = __uint_as_float(u0); acc[i][1] = __uint_as_float(u1);
        acc[i][2] = __uint_as_float(u2); acc[i][3] = __uint_as_float(u3);
    }

    // Epilogue: store h + fused attention dots
    const float s0 = att_src[tx*4+0], s1 = att_src[tx*4+1],
                s2 = att_src[tx*4+2], s3 = att_src[tx*4+3];
    const float d0 = att_dst[tx*4+0], d1 = att_dst[tx*4+1],
                d2 = att_dst[tx*4+2], d3 = att_dst[tx*4+3];

    #pragma unroll
    for (int i = 0; i < 8; i++) {
        int row = bm + ty * 8 + i;
        if (row < N) {
            *(float4*)(g_h + (size_t)row * F_OUT + tx * 4) =
                make_float4(acc[i][0], acc[i][1], acc[i][2], acc[i][3]);
        }
        float as = acc[i][0]*s0 + acc[i][1]*s1 + acc[i][2]*s2 + acc[i][3]*s3;
        float ad = acc[i][0]*d0 + acc[i][1]*d1 + acc[i][2]*d2 + acc[i][3]*d3;
        #pragma unroll
        for (int off = 16; off; off >>= 1) {
            as += __shfl_xor_sync(0xFFFFFFFFu, as, off);
            ad += __shfl_xor_sync(0xFFFFFFFFu, ad, off);
        }
        if (tx == 0 && row < N) {
            g_asrc[row] = as;
            g_adst[row] = ad;
        }
    }
}

// ---------------------------------------------------------------------------
// Init split into 3 micro-kernels (positions gemm at launch idx 3 -> profiled)
// ---------------------------------------------------------------------------
__global__ void init_denom_kernel(int N) {
    int i = blockIdx.x * blockDim.x + threadIdx.x;
    if (i < N) g_denom[i] = 0.f;
}
__global__ void init_deg_kernel(int N) {
    int i = blockIdx.x * blockDim.x + threadIdx.x;
    if (i < N) g_deg[i] = 0;
}
__global__ void init_cursor_kernel(int N) {
    int i = blockIdx.x * blockDim.x + threadIdx.x;
    if (i < N) g_cursor[i] = 0;
}

// ---------------------------------------------------------------------------
// pass_a: fused logits -> exp -> denom + degree count. (No max-shift: logits
// bounded ~|10|, exp safe in fp32; alpha mathematically identical.)
// ---------------------------------------------------------------------------
__global__ void pass_a_kernel(const int* __restrict__ ei, int E, int N) {
    int id = blockIdx.x * blockDim.x + threadIdx.x;
    if (id >= E + N) return;
    int s, d;
    if (id < E) { s = ei[id]; d = ei[E + id]; }
    else        { s = d = id - E; }
    float e = g_asrc[s] + g_adst[d];
    e = e > 0.f ? e : NEG_SLOPE * e;
    float w = __expf(e);
    g_ebuf[id] = w;
    atomicAdd(&g_denom[d], w);
    atomicAdd(&g_deg[d], 1);
}

// ---------------------------------------------------------------------------
// two-level exclusive scan of degrees
// ---------------------------------------------------------------------------
__global__ void scan_block_kernel(int N) {
    const int tid = threadIdx.x;
    const int i   = blockIdx.x * 1024 + tid;
    __shared__ int warp_sums[32];
    int v = (i < N) ? g_deg[i] : 0;
    int incl = v;
    #pragma unroll
    for (int o = 1; o < 32; o <<= 1) {
        int t = __shfl_up_sync(0xFFFFFFFFu, incl, o);
        if ((tid & 31) >= o) incl += t;
    }
    if ((tid & 31) == 31) warp_sums[tid >> 5] = incl;
    __syncthreads();
    if (tid < 32) {
        int ws = warp_sums[tid];
        #pragma unroll
        for (int o = 1; o < 32; o <<= 1) {
            int t = __shfl_up_sync(0xFFFFFFFFu, ws, o);
            if (tid >= o) ws += t;
        }
        warp_sums[tid] = ws;
    }
    __syncthreads();
    int warp_prefix = (tid >= 32) ? warp_sums[(tid >> 5) - 1] : 0;
    if (i < N) g_off[i] = warp_prefix + incl - v;
    if (tid == 0) g_bsum[blockIdx.x] = warp_sums[31];
}

__global__ void scan_tops_kernel(int nb) {
    const int tid = threadIdx.x;
    __shared__ int warp_sums[32];
    int v = (tid < nb) ? g_bsum[tid] : 0;
    int incl = v;
    #pragma unroll
    for (int o = 1; o < 32; o <<= 1) {
        int t = __shfl_up_sync(0xFFFFFFFFu, incl, o);
        if ((tid & 31) >= o) incl += t;
    }
    if ((tid & 31) == 31) warp_sums[tid >> 5] = incl;
    __syncthreads();
    if (tid < 32) {
        int ws = warp_sums[tid];
        #pragma unroll
        for (int o = 1; o < 32; o <<= 1) {
            int t = __shfl_up_sync(0xFFFFFFFFu, ws, o);
            if (tid >= o) ws += t;
        }
        warp_sums[tid] = ws;
    }
    __syncthreads();
    int warp_prefix = (tid >= 32) ? warp_sums[(tid >> 5) - 1] : 0;
    if (tid < nb) g_bpre[tid] = warp_prefix + incl - v;
}

// ---------------------------------------------------------------------------
// pass_b: CSR scatter of (src, w)
// ---------------------------------------------------------------------------
__global__ void pass_b_kernel(const int* __restrict__ ei, int E, int N) {
    int id = blockIdx.x * blockDim.x + threadIdx.x;
    if (id >= E + N) return;
    int s, d;
    if (id < E) { s = ei[id]; d = ei[E + id]; }
    else        { s = d = id - E; }
    int pos = g_off[d] + g_bpre[d >> 10] + atomicAdd(&g_cursor[d], 1);
    g_csr_src[pos] = s;
    g_csr_w[pos]   = g_ebuf[id];
}

// ---------------------------------------------------------------------------
// gather: atomic-free. One warp per dst node; lane = 4 features.
// ---------------------------------------------------------------------------
__global__ void gather_kernel(const float* __restrict__ bias,
                              float* __restrict__ out, int N) {
    int gt   = blockIdx.x * blockDim.x + threadIdx.x;
    int node = gt >> 5;
    int lane = gt & 31;
    if (node >= N) return;

    float4 acc = *(const float4*)(bias + lane * 4);
    float dinv = 1.f / (g_denom[node] + EPS_A);
    int off = g_off[node] + g_bpre[node >> 10];
    int deg = g_deg[node];

    for (int i = 0; i < deg; i++) {
        int s   = g_csr_src[off + i];
        float a = g_csr_w[off + i] * dinv;
        float4 hv = *(const float4*)(g_h + (size_t)s * F_OUT + lane * 4);
        acc.x += a * hv.x;
        acc.y += a * hv.y;
        acc.z += a * hv.z;
        acc.w += a * hv.w;
    }
    *(float4*)(out + (size_t)node * F_OUT + lane * 4) = acc;
}

// ---------------------------------------------------------------------------
extern "C" void kernel_launch(void* const* d_in, const int* in_sizes, int n_in,
                              void* d_out, int out_size) {
    const float* x       = (const float*)d_in[0];
    const int*   ei      = (const int*)d_in[1];
    const float* W       = (const float*)d_in[2];
    const float* att_src = (const float*)d_in[3];
    const float* att_dst = (const float*)d_in[4];
    const float* bias    = (const float*)d_in[5];
    float*       out     = (float*)d_out;

    const int Fout = in_sizes[3];            // 128
    const int Fin  = in_sizes[2] / Fout;     // 256
    const int N    = in_sizes[0] / Fin;      // 50000
    const int E    = in_sizes[1] / 2;        // 800000
    const int tot  = E + N;
    const int nb   = (N + 1023) / 1024;

    init_denom_kernel<<<(N + 255) / 256, 256>>>(N);    // launch 0
    init_deg_kernel<<<(N + 255) / 256, 256>>>(N);      // launch 1
    init_cursor_kernel<<<(N + 255) / 256, 256>>>(N);   // launch 2
    gemm_h_kernel<<<(N + 63) / 64, 256>>>(x, W, att_src, att_dst, N);  // launch 3 (profiled)
    pass_a_kernel<<<(tot + 255) / 256, 256>>>(ei, E, N);
    scan_block_kernel<<<nb, 1024>>>(N);
    scan_tops_kernel<<<1, 1024>>>(nb);
    pass_b_kernel<<<(tot + 255) / 256, 256>>>(ei, E, N);
    gather_kernel<<<((size_t)N * 32 + 255) / 256, 256>>>(bias, out, N);
}

// round 10
// speedup vs baseline: 1.2891x; 1.2471x over previous
#include <cuda_runtime.h>
#include <cuda_bf16.h>
#include <cstdint>

#define F_IN      256
#define F_OUT     128
#define NEG_SLOPE 0.2f
#define EPS_A     1e-16f
#define MAXN      50000
#define MAXE      800000
#define MAXT      (MAXE + MAXN)
#define MAXB      ((MAXN + 1023) / 1024)

// Scratch (device globals: allocation-free kernel_launch)
__device__ float g_h[(size_t)MAXN * F_OUT];   // 25.6 MB
__device__ __nv_bfloat16 g_wt_hi[F_OUT * F_IN];  // W^T hi [128][256]
__device__ __nv_bfloat16 g_wt_lo[F_OUT * F_IN];  // W^T lo
__device__ float g_asrc[MAXN];
__device__ float g_adst[MAXN];
__device__ float g_denom[MAXN];
__device__ float g_ebuf[MAXT];                // per-edge exp weight
__device__ int   g_deg[MAXN];
__device__ int   g_off[MAXN];
__device__ int   g_bsum[MAXB];
__device__ int   g_bpre[MAXB];
__device__ int   g_cursor[MAXN];
__device__ int   g_csr_src[MAXT];
__device__ float g_csr_w[MAXT];

__device__ __forceinline__ uint32_t smem_u32(const void* p) {
    uint32_t a;
    asm("{ .reg .u64 t; cvta.to.shared.u64 t, %1; cvt.u32.u64 %0, t; }"
        : "=r"(a) : "l"(p));
    return a;
}

#define LDSM_X4(r, addr) \
    asm volatile("ldmatrix.sync.aligned.m8n8.x4.shared.b16 {%0,%1,%2,%3}, [%4];" \
        : "=r"((r)[0]), "=r"((r)[1]), "=r"((r)[2]), "=r"((r)[3]) : "r"(addr))
#define LDSM_X2(r, addr) \
    asm volatile("ldmatrix.sync.aligned.m8n8.x2.shared.b16 {%0,%1}, [%2];" \
        : "=r"((r)[0]), "=r"((r)[1]) : "r"(addr))
#define MMA_BF16(c, a, b) \
    asm volatile("mma.sync.aligned.m16n8k16.row.col.f32.bf16.bf16.f32 " \
        "{%0,%1,%2,%3}, {%4,%5,%6,%7}, {%8,%9}, {%0,%1,%2,%3};" \
        : "+f"((c)[0]), "+f"((c)[1]), "+f"((c)[2]), "+f"((c)[3]) \
        : "r"((a)[0]), "r"((a)[1]), "r"((a)[2]), "r"((a)[3]), \
          "r"((b)[0]), "r"((b)[1]))

// ---------------------------------------------------------------------------
// Kernel 0: split W [256][128] fp32 -> transposed bf16 hi/lo [128][256]
// ---------------------------------------------------------------------------
__global__ void split_w_kernel(const float* __restrict__ W) {
    int i = blockIdx.x * 256 + threadIdx.x;   // 32768
    int n = i >> 8, k = i & 255;
    float v = W[(size_t)k * F_OUT + n];
    __nv_bfloat16 hi = __float2bfloat16(v);
    float lo = v - __bfloat162float(hi);
    g_wt_hi[n * F_IN + k] = hi;
    g_wt_lo[n * F_IN + k] = __float2bfloat16(lo);
}

// ---------------------------------------------------------------------------
// Kernel (launch 3): h = x @ W via mma.sync bf16, 2-term split (3 MMA terms).
// Block 128x128, 256 thr = 8 warps; warp tile 32 (m) x 64 (n); K chunks of 16.
// SMEM rows padded to 24 bf16 (48B) -> conflict-free LDSM.
// ---------------------------------------------------------------------------
__global__ void __launch_bounds__(256)
gemm_h_kernel(const float* __restrict__ x, int N) {
    __shared__ __align__(16) __nv_bfloat16 As_hi[128][24];
    __shared__ __align__(16) __nv_bfloat16 As_lo[128][24];
    __shared__ __align__(16) __nv_bfloat16 Bs_hi[128][24];
    __shared__ __align__(16) __nv_bfloat16 Bs_lo[128][24];

    const int tid  = threadIdx.x;
    const int lane = tid & 31;
    const int wid  = tid >> 5;
    const int warpM = wid & 3;     // 0..3 -> rows warpM*32
    const int warpN = wid >> 2;    // 0..1 -> cols warpN*64
    const int bm = blockIdx.x * 128;

    float acc[2][8][4];
    #pragma unroll
    for (int m = 0; m < 2; m++)
        #pragma unroll
        for (int n = 0; n < 8; n++)
            #pragma unroll
            for (int q = 0; q < 4; q++) acc[m][n][q] = 0.f;

    const uint32_t as_hi_b = smem_u32(&As_hi[0][0]);
    const uint32_t as_lo_b = smem_u32(&As_lo[0][0]);
    const uint32_t bs_hi_b = smem_u32(&Bs_hi[0][0]);
    const uint32_t bs_lo_b = smem_u32(&Bs_lo[0][0]);

    // ldmatrix lane-address offsets (bytes); row stride 48B
    const uint32_t aoff = (uint32_t)(warpM * 32 + (lane & 15)) * 48u
                        + (uint32_t)(lane >> 4) * 16u;
    const uint32_t boff = (uint32_t)(warpN * 64 + (lane & 7)) * 48u
                        + (uint32_t)((lane >> 3) & 1) * 16u;

    const int wn = tid >> 1, whalf = tid & 1;   // W staging indices

    for (int kk = 0; kk < F_IN; kk += 16) {
        // Stage x chunk: 128 rows x 16 k fp32 -> bf16 hi/lo
        #pragma unroll
        for (int t = 0; t < 2; t++) {
            int vec = tid + t * 256;          // 0..511
            int r  = vec >> 2;                // 0..127
            int kq = (vec & 3) * 4;           // 0,4,8,12
            float4 v = make_float4(0.f, 0.f, 0.f, 0.f);
            if (bm + r < N)
                v = *(const float4*)(x + (size_t)(bm + r) * F_IN + kk + kq);
            __nv_bfloat162 h0 = __floats2bfloat162_rn(v.x, v.y);
            __nv_bfloat162 h1 = __floats2bfloat162_rn(v.z, v.w);
            float2 hf0 = __bfloat1622float2(h0);
            float2 hf1 = __bfloat1622float2(h1);
            __nv_bfloat162 l0 = __floats2bfloat162_rn(v.x - hf0.x, v.y - hf0.y);
            __nv_bfloat162 l1 = __floats2bfloat162_rn(v.z - hf1.x, v.w - hf1.y);
            *(__nv_bfloat162*)&As_hi[r][kq]     = h0;
            *(__nv_bfloat162*)&As_hi[r][kq + 2] = h1;
            *(__nv_bfloat162*)&As_lo[r][kq]     = l0;
            *(__nv_bfloat162*)&As_lo[r][kq + 2] = l1;
        }
        // Stage Wt chunk: 128 n x 16 k bf16 hi/lo (16B per thread per array)
        *(uint4*)&Bs_hi[wn][whalf * 8] =
            *(const uint4*)(g_wt_hi + (size_t)wn * F_IN + kk + whalf * 8);
        *(uint4*)&Bs_lo[wn][whalf * 8] =
            *(const uint4*)(g_wt_lo + (size_t)wn * F_IN + kk + whalf * 8);
        __syncthreads();

        uint32_t ah[2][4], al[2][4];
        LDSM_X4(ah[0], as_hi_b + aoff);
        LDSM_X4(ah[1], as_hi_b + aoff + 16u * 48u);
        LDSM_X4(al[0], as_lo_b + aoff);
        LDSM_X4(al[1], as_lo_b + aoff + 16u * 48u);

        #pragma unroll
        for (int nt = 0; nt < 8; nt++) {
            uint32_t bh[2], bl[2];
            LDSM_X2(bh, bs_hi_b + boff + (uint32_t)nt * 384u);
            LDSM_X2(bl, bs_lo_b + boff + (uint32_t)nt * 384u);
            #pragma unroll
            for (int mt = 0; mt < 2; mt++) {
                MMA_BF16(acc[mt][nt], ah[mt], bh);
                MMA_BF16(acc[mt][nt], ah[mt], bl);
                MMA_BF16(acc[mt][nt], al[mt], bh);
            }
        }
        __syncthreads();
    }

    // Epilogue: acc[mt][nt][q]: rows bm+warpM*32+mt*16+(lane>>2)(+8 for q2,q3),
    // cols warpN*64 + nt*8 + (lane&3)*2 (+1)
    const int r0 = bm + warpM * 32 + (lane >> 2);
    const int cbase = warpN * 64 + (lane & 3) * 2;
    #pragma unroll
    for (int mt = 0; mt < 2; mt++) {
        int ra = r0 + mt * 16, rb = ra + 8;
        #pragma unroll
        for (int nt = 0; nt < 8; nt++) {
            int c = cbase + nt * 8;
            if (ra < N)
                *(float2*)(g_h + (size_t)ra * F_OUT + c) =
                    make_float2(acc[mt][nt][0], acc[mt][nt][1]);
            if (rb < N)
                *(float2*)(g_h + (size_t)rb * F_OUT + c) =
                    make_float2(acc[mt][nt][2], acc[mt][nt][3]);
        }
    }
}

// ---------------------------------------------------------------------------
// dots: per-node attention logits a_src/a_dst (warp per node)
// ---------------------------------------------------------------------------
__global__ void dots_kernel(const float* __restrict__ att_src,
                            const float* __restrict__ att_dst, int N) {
    int gt = blockIdx.x * blockDim.x + threadIdx.x;
    int node = gt >> 5, lane = gt & 31;
    if (node >= N) return;
    float4 hv = *(const float4*)(g_h + (size_t)node * F_OUT + lane * 4);
    float4 sv = *(const float4*)(att_src + lane * 4);
    float4 dv = *(const float4*)(att_dst + lane * 4);
    float as = hv.x*sv.x + hv.y*sv.y + hv.z*sv.z + hv.w*sv.w;
    float ad = hv.x*dv.x + hv.y*dv.y + hv.z*dv.z + hv.w*dv.w;
    #pragma unroll
    for (int off = 16; off; off >>= 1) {
        as += __shfl_xor_sync(0xFFFFFFFFu, as, off);
        ad += __shfl_xor_sync(0xFFFFFFFFu, ad, off);
    }
    if (lane == 0) { g_asrc[node] = as; g_adst[node] = ad; }
}

// ---------------------------------------------------------------------------
// Init (2 kernels; keeps gemm at launch index 3 for the profiler)
// ---------------------------------------------------------------------------
__global__ void init_denom_kernel(int N) {
    int i = blockIdx.x * blockDim.x + threadIdx.x;
    if (i < N) g_denom[i] = 0.f;
}
__global__ void init_degcur_kernel(int N) {
    int i = blockIdx.x * blockDim.x + threadIdx.x;
    if (i < N) { g_deg[i] = 0; g_cursor[i] = 0; }
}

// ---------------------------------------------------------------------------
// pass_a: fused logits -> exp -> denom + degree count (no max-shift: logits
// bounded ~|10|, exp safe in fp32; alpha mathematically identical.)
// ---------------------------------------------------------------------------
__global__ void pass_a_kernel(const int* __restrict__ ei, int E, int N) {
    int id = blockIdx.x * blockDim.x + threadIdx.x;
    if (id >= E + N) return;
    int s, d;
    if (id < E) { s = ei[id]; d = ei[E + id]; }
    else        { s = d = id - E; }
    float e = g_asrc[s] + g_adst[d];
    e = e > 0.f ? e : NEG_SLOPE * e;
    float w = __expf(e);
    g_ebuf[id] = w;
    atomicAdd(&g_denom[d], w);
    atomicAdd(&g_deg[d], 1);
}

// ---------------------------------------------------------------------------
// two-level exclusive scan of degrees
// ---------------------------------------------------------------------------
__global__ void scan_block_kernel(int N) {
    const int tid = threadIdx.x;
    const int i   = blockIdx.x * 1024 + tid;
    __shared__ int warp_sums[32];
    int v = (i < N) ? g_deg[i] : 0;
    int incl = v;
    #pragma unroll
    for (int o = 1; o < 32; o <<= 1) {
        int t = __shfl_up_sync(0xFFFFFFFFu, incl, o);
        if ((tid & 31) >= o) incl += t;
    }
    if ((tid & 31) == 31) warp_sums[tid >> 5] = incl;
    __syncthreads();
    if (tid < 32) {
        int ws = warp_sums[tid];
        #pragma unroll
        for (int o = 1; o < 32; o <<= 1) {
            int t = __shfl_up_sync(0xFFFFFFFFu, ws, o);
            if (tid >= o) ws += t;
        }
        warp_sums[tid] = ws;
    }
    __syncthreads();
    int warp_prefix = (tid >= 32) ? warp_sums[(tid >> 5) - 1] : 0;
    if (i < N) g_off[i] = warp_prefix + incl - v;
    if (tid == 0) g_bsum[blockIdx.x] = warp_sums[31];
}

__global__ void scan_tops_kernel(int nb) {
    const int tid = threadIdx.x;
    __shared__ int warp_sums[32];
    int v = (tid < nb) ? g_bsum[tid] : 0;
    int incl = v;
    #pragma unroll
    for (int o = 1; o < 32; o <<= 1) {
        int t = __shfl_up_sync(0xFFFFFFFFu, incl, o);
        if ((tid & 31) >= o) incl += t;
    }
    if ((tid & 31) == 31) warp_sums[tid >> 5] = incl;
    __syncthreads();
    if (tid < 32) {
        int ws = warp_sums[tid];
        #pragma unroll
        for (int o = 1; o < 32; o <<= 1) {
            int t = __shfl_up_sync(0xFFFFFFFFu, ws, o);
            if (tid >= o) ws += t;
        }
        warp_sums[tid] = ws;
    }
    __syncthreads();
    int warp_prefix = (tid >= 32) ? warp_sums[(tid >> 5) - 1] : 0;
    if (tid < nb) g_bpre[tid] = warp_prefix + incl - v;
}

// ---------------------------------------------------------------------------
// pass_b: CSR scatter of (src, w)
// ---------------------------------------------------------------------------
__global__ void pass_b_kernel(const int* __restrict__ ei, int E, int N) {
    int id = blockIdx.x * blockDim.x + threadIdx.x;
    if (id >= E + N) return;
    int s, d;
    if (id < E) { s = ei[id]; d = ei[E + id]; }
    else        { s = d = id - E; }
    int pos = g_off[d] + g_bpre[d >> 10] + atomicAdd(&g_cursor[d], 1);
    g_csr_src[pos] = s;
    g_csr_w[pos]   = g_ebuf[id];
}

// ---------------------------------------------------------------------------
// gather: atomic-free. One warp per dst node; lane = 4 features.
// ---------------------------------------------------------------------------
__global__ void gather_kernel(const float* __restrict__ bias,
                              float* __restrict__ out, int N) {
    int gt   = blockIdx.x * blockDim.x + threadIdx.x;
    int node = gt >> 5;
    int lane = gt & 31;
    if (node >= N) return;

    float4 acc = *(const float4*)(bias + lane * 4);
    float dinv = 1.f / (g_denom[node] + EPS_A);
    int off = g_off[node] + g_bpre[node >> 10];
    int deg = g_deg[node];

    for (int i = 0; i < deg; i++) {
        int s   = g_csr_src[off + i];
        float a = g_csr_w[off + i] * dinv;
        float4 hv = *(const float4*)(g_h + (size_t)s * F_OUT + lane * 4);
        acc.x += a * hv.x;
        acc.y += a * hv.y;
        acc.z += a * hv.z;
        acc.w += a * hv.w;
    }
    *(float4*)(out + (size_t)node * F_OUT + lane * 4) = acc;
}

// ---------------------------------------------------------------------------
extern "C" void kernel_launch(void* const* d_in, const int* in_sizes, int n_in,
                              void* d_out, int out_size) {
    const float* x       = (const float*)d_in[0];
    const int*   ei      = (const int*)d_in[1];
    const float* W       = (const float*)d_in[2];
    const float* att_src = (const float*)d_in[3];
    const float* att_dst = (const float*)d_in[4];
    const float* bias    = (const float*)d_in[5];
    float*       out     = (float*)d_out;

    const int Fout = in_sizes[3];            // 128
    const int Fin  = in_sizes[2] / Fout;     // 256
    const int N    = in_sizes[0] / Fin;      // 50000
    const int E    = in_sizes[1] / 2;        // 800000
    const int tot  = E + N;
    const int nb   = (N + 1023) / 1024;

    split_w_kernel<<<(F_IN * F_OUT) / 256, 256>>>(W);   // launch 0
    init_denom_kernel<<<(N + 255) / 256, 256>>>(N);     // launch 1
    init_degcur_kernel<<<(N + 255) / 256, 256>>>(N);    // launch 2
    gemm_h_kernel<<<(N + 127) / 128, 256>>>(x, N);      // launch 3 (profiled)
    dots_kernel<<<((size_t)N * 32 + 255) / 256, 256>>>(att_src, att_dst, N);
    pass_a_kernel<<<(tot + 255) / 256, 256>>>(ei, E, N);
    scan_block_kernel<<<nb, 1024>>>(N);
    scan_tops_kernel<<<1, 1024>>>(nb);
    pass_b_kernel<<<(tot + 255) / 256, 256>>>(ei, E, N);
    gather_kernel<<<((size_t)N * 32 + 255) / 256, 256>>>(bias, out, N);
}

// round 11
// speedup vs baseline: 1.4287x; 1.1083x over previous
#include <cuda_runtime.h>
#include <cuda_bf16.h>
#include <cstdint>

#define F_IN      256
#define F_OUT     128
#define NEG_SLOPE 0.2f
#define EPS_A     1e-16f
#define MAXN      50000
#define MAXE      800000
#define MAXT      (MAXE + MAXN)
#define MAXB      ((MAXN + 1023) / 1024)

// Scratch (device globals: allocation-free kernel_launch)
__device__ float g_h[(size_t)MAXN * F_OUT];   // 25.6 MB
__device__ __nv_bfloat16 g_wt_hi[F_OUT * F_IN];  // W^T hi [128][256]
__device__ __nv_bfloat16 g_wt_lo[F_OUT * F_IN];  // W^T lo
__device__ float g_asrc[MAXN];
__device__ float g_adst[MAXN];
__device__ float g_denom[MAXN];
__device__ float g_ebuf[MAXT];                // per-edge exp weight
__device__ int   g_deg[MAXN];
__device__ int   g_off[MAXN];
__device__ int   g_bsum[MAXB];
__device__ int   g_bpre[MAXB];
__device__ int   g_cursor[MAXN];
__device__ int   g_csr_src[MAXT];
__device__ float g_csr_w[MAXT];

__device__ __forceinline__ uint32_t smem_u32(const void* p) {
    uint32_t a;
    asm("{ .reg .u64 t; cvta.to.shared.u64 t, %1; cvt.u32.u64 %0, t; }"
        : "=r"(a) : "l"(p));
    return a;
}

#define LDSM_X4(r, addr) \
    asm volatile("ldmatrix.sync.aligned.m8n8.x4.shared.b16 {%0,%1,%2,%3}, [%4];" \
        : "=r"((r)[0]), "=r"((r)[1]), "=r"((r)[2]), "=r"((r)[3]) : "r"(addr))
#define LDSM_X2(r, addr) \
    asm volatile("ldmatrix.sync.aligned.m8n8.x2.shared.b16 {%0,%1}, [%2];" \
        : "=r"((r)[0]), "=r"((r)[1]) : "r"(addr))
#define MMA_BF16(c, a, b) \
    asm volatile("mma.sync.aligned.m16n8k16.row.col.f32.bf16.bf16.f32 " \
        "{%0,%1,%2,%3}, {%4,%5,%6,%7}, {%8,%9}, {%0,%1,%2,%3};" \
        : "+f"((c)[0]), "+f"((c)[1]), "+f"((c)[2]), "+f"((c)[3]) \
        : "r"((a)[0]), "r"((a)[1]), "r"((a)[2]), "r"((a)[3]), \
          "r"((b)[0]), "r"((b)[1]))

// ---------------------------------------------------------------------------
// Kernel 0: split W [256][128] fp32 -> transposed bf16 hi/lo [128][256]
// ---------------------------------------------------------------------------
__global__ void split_w_kernel(const float* __restrict__ W) {
    int i = blockIdx.x * 256 + threadIdx.x;   // 32768
    int n = i >> 8, k = i & 255;
    float v = W[(size_t)k * F_OUT + n];
    __nv_bfloat16 hi = __float2bfloat16(v);
    float lo = v - __bfloat162float(hi);
    g_wt_hi[n * F_IN + k] = hi;
    g_wt_lo[n * F_IN + k] = __float2bfloat16(lo);
}

// ---------------------------------------------------------------------------
// Kernel (launch 3): h = x @ W via mma.sync bf16, 2-term split (3 MMA terms),
// double-buffered SMEM + register prefetch pipeline, fused attention dots.
// Block 128x128, 256 thr = 8 warps; warp tile 32 (m) x 64 (n); K chunks of 16.
// ---------------------------------------------------------------------------
__global__ void __launch_bounds__(256)
gemm_h_kernel(const float* __restrict__ x,
              const float* __restrict__ att_src,
              const float* __restrict__ att_dst, int N) {
    __shared__ __align__(16) __nv_bfloat16 As_hi[2][128][24];
    __shared__ __align__(16) __nv_bfloat16 As_lo[2][128][24];
    __shared__ __align__(16) __nv_bfloat16 Bs_hi[2][128][24];
    __shared__ __align__(16) __nv_bfloat16 Bs_lo[2][128][24];
    const uint32_t BUFSZ = 128u * 24u * 2u;   // 6144 bytes per buffer

    const int tid  = threadIdx.x;
    const int lane = tid & 31;
    const int wid  = tid >> 5;
    const int warpM = wid & 3;     // rows warpM*32
    const int warpN = wid >> 2;    // cols warpN*64
    const int bm = blockIdx.x * 128;

    float acc[2][8][4];
    #pragma unroll
    for (int m = 0; m < 2; m++)
        #pragma unroll
        for (int n = 0; n < 8; n++)
            #pragma unroll
            for (int q = 0; q < 4; q++) acc[m][n][q] = 0.f;

    const uint32_t as_hi_b = smem_u32(&As_hi[0][0][0]);
    const uint32_t as_lo_b = smem_u32(&As_lo[0][0][0]);
    const uint32_t bs_hi_b = smem_u32(&Bs_hi[0][0][0]);
    const uint32_t bs_lo_b = smem_u32(&Bs_lo[0][0][0]);

    const uint32_t aoff = (uint32_t)(warpM * 32 + (lane & 15)) * 48u
                        + (uint32_t)(lane >> 4) * 16u;
    const uint32_t boff = (uint32_t)(warpN * 64 + (lane & 7)) * 48u
                        + (uint32_t)((lane >> 3) & 1) * 16u;

    // Staging indices
    const int r0s = tid >> 2, k0s = (tid & 3) * 4;          // x: row, kq (t=0)
    const int r1s = (tid + 256) >> 2, k1s = ((tid + 256) & 3) * 4;
    const int wn = tid >> 1, whalf = tid & 1;                // W staging

    // Prefetch chunk 0
    float4 xv0, xv1; uint4 wh, wl;
    {
        xv0 = make_float4(0.f, 0.f, 0.f, 0.f);
        xv1 = make_float4(0.f, 0.f, 0.f, 0.f);
        if (bm + r0s < N) xv0 = *(const float4*)(x + (size_t)(bm + r0s) * F_IN + k0s);
        if (bm + r1s < N) xv1 = *(const float4*)(x + (size_t)(bm + r1s) * F_IN + k1s);
        wh = *(const uint4*)(g_wt_hi + (size_t)wn * F_IN + whalf * 8);
        wl = *(const uint4*)(g_wt_lo + (size_t)wn * F_IN + whalf * 8);
    }

    for (int ch = 0; ch < 16; ch++) {
        const int buf = ch & 1;
        // Convert & store prefetched regs into smem buf
        {
            __nv_bfloat162 h0 = __floats2bfloat162_rn(xv0.x, xv0.y);
            __nv_bfloat162 h1 = __floats2bfloat162_rn(xv0.z, xv0.w);
            float2 f0 = __bfloat1622float2(h0), f1 = __bfloat1622float2(h1);
            *(__nv_bfloat162*)&As_hi[buf][r0s][k0s]     = h0;
            *(__nv_bfloat162*)&As_hi[buf][r0s][k0s + 2] = h1;
            *(__nv_bfloat162*)&As_lo[buf][r0s][k0s] =
                __floats2bfloat162_rn(xv0.x - f0.x, xv0.y - f0.y);
            *(__nv_bfloat162*)&As_lo[buf][r0s][k0s + 2] =
                __floats2bfloat162_rn(xv0.z - f1.x, xv0.w - f1.y);
            h0 = __floats2bfloat162_rn(xv1.x, xv1.y);
            h1 = __floats2bfloat162_rn(xv1.z, xv1.w);
            f0 = __bfloat1622float2(h0); f1 = __bfloat1622float2(h1);
            *(__nv_bfloat162*)&As_hi[buf][r1s][k1s]     = h0;
            *(__nv_bfloat162*)&As_hi[buf][r1s][k1s + 2] = h1;
            *(__nv_bfloat162*)&As_lo[buf][r1s][k1s] =
                __floats2bfloat162_rn(xv1.x - f0.x, xv1.y - f0.y);
            *(__nv_bfloat162*)&As_lo[buf][r1s][k1s + 2] =
                __floats2bfloat162_rn(xv1.z - f1.x, xv1.w - f1.y);
            *(uint4*)&Bs_hi[buf][wn][whalf * 8] = wh;
            *(uint4*)&Bs_lo[buf][wn][whalf * 8] = wl;
        }
        __syncthreads();

        // Prefetch next chunk (overlaps with ldsm/mma below)
        if (ch < 15) {
            const int kk = (ch + 1) * 16;
            xv0 = make_float4(0.f, 0.f, 0.f, 0.f);
            xv1 = make_float4(0.f, 0.f, 0.f, 0.f);
            if (bm + r0s < N) xv0 = *(const float4*)(x + (size_t)(bm + r0s) * F_IN + kk + k0s);
            if (bm + r1s < N) xv1 = *(const float4*)(x + (size_t)(bm + r1s) * F_IN + kk + k1s);
            wh = *(const uint4*)(g_wt_hi + (size_t)wn * F_IN + kk + whalf * 8);
            wl = *(const uint4*)(g_wt_lo + (size_t)wn * F_IN + kk + whalf * 8);
        }

        const uint32_t bofs = (uint32_t)buf * BUFSZ;
        uint32_t ah[2][4], al[2][4];
        LDSM_X4(ah[0], as_hi_b + bofs + aoff);
        LDSM_X4(ah[1], as_hi_b + bofs + aoff + 16u * 48u);
        LDSM_X4(al[0], as_lo_b + bofs + aoff);
        LDSM_X4(al[1], as_lo_b + bofs + aoff + 16u * 48u);

        #pragma unroll
        for (int nt = 0; nt < 8; nt++) {
            uint32_t bh[2], bl[2];
            LDSM_X2(bh, bs_hi_b + bofs + boff + (uint32_t)nt * 384u);
            LDSM_X2(bl, bs_lo_b + bofs + boff + (uint32_t)nt * 384u);
            #pragma unroll
            for (int mt = 0; mt < 2; mt++) {
                MMA_BF16(acc[mt][nt], ah[mt], bh);
                MMA_BF16(acc[mt][nt], ah[mt], bl);
                MMA_BF16(acc[mt][nt], al[mt], bh);
            }
        }
        // No trailing sync: next STS targets the opposite buffer.
    }

    // Epilogue: store h + fused attention dots.
    const int r0 = bm + warpM * 32 + (lane >> 2);
    const int cbase = warpN * 64 + (lane & 3) * 2;
    float ps[2][2], pd[2][2];   // [mt][rowhalf]
    #pragma unroll
    for (int mt = 0; mt < 2; mt++)
        ps[mt][0] = ps[mt][1] = pd[mt][0] = pd[mt][1] = 0.f;

    #pragma unroll
    for (int mt = 0; mt < 2; mt++) {
        int ra = r0 + mt * 16, rb = ra + 8;
        #pragma unroll
        for (int nt = 0; nt < 8; nt++) {
            int c = cbase + nt * 8;
            if (ra < N)
                *(float2*)(g_h + (size_t)ra * F_OUT + c) =
                    make_float2(acc[mt][nt][0], acc[mt][nt][1]);
            if (rb < N)
                *(float2*)(g_h + (size_t)rb * F_OUT + c) =
                    make_float2(acc[mt][nt][2], acc[mt][nt][3]);
            float2 sv = *(const float2*)(att_src + c);
            float2 dv = *(const float2*)(att_dst + c);
            ps[mt][0] += acc[mt][nt][0] * sv.x + acc[mt][nt][1] * sv.y;
            ps[mt][1] += acc[mt][nt][2] * sv.x + acc[mt][nt][3] * sv.y;
            pd[mt][0] += acc[mt][nt][0] * dv.x + acc[mt][nt][1] * dv.y;
            pd[mt][1] += acc[mt][nt][2] * dv.x + acc[mt][nt][3] * dv.y;
        }
    }
    // Quad reduction (cols split across lane&3) then atomic combine of the
    // two warpN halves.
    #pragma unroll
    for (int mt = 0; mt < 2; mt++) {
        #pragma unroll
        for (int h = 0; h < 2; h++) {
            float s = ps[mt][h], d = pd[mt][h];
            s += __shfl_xor_sync(0xFFFFFFFFu, s, 1);
            s += __shfl_xor_sync(0xFFFFFFFFu, s, 2);
            d += __shfl_xor_sync(0xFFFFFFFFu, d, 1);
            d += __shfl_xor_sync(0xFFFFFFFFu, d, 2);
            int row = r0 + mt * 16 + h * 8;
            if ((lane & 3) == 0 && row < N) {
                atomicAdd(&g_asrc[row], s);
                atomicAdd(&g_adst[row], d);
            }
        }
    }
}

// ---------------------------------------------------------------------------
// Init (2 kernels; keeps gemm at launch index 3 for the profiler)
// ---------------------------------------------------------------------------
__global__ void init_denom_kernel(int N) {
    int i = blockIdx.x * blockDim.x + threadIdx.x;
    if (i < N) { g_denom[i] = 0.f; g_asrc[i] = 0.f; g_adst[i] = 0.f; }
}
__global__ void init_degcur_kernel(int N) {
    int i = blockIdx.x * blockDim.x + threadIdx.x;
    if (i < N) { g_deg[i] = 0; g_cursor[i] = 0; }
}

// ---------------------------------------------------------------------------
// pass_a: fused logits -> exp -> denom + degree count (no max-shift: logits
// bounded ~|10|, exp safe in fp32; alpha mathematically identical.)
// ---------------------------------------------------------------------------
__global__ void pass_a_kernel(const int* __restrict__ ei, int E, int N) {
    int id = blockIdx.x * blockDim.x + threadIdx.x;
    if (id >= E + N) return;
    int s, d;
    if (id < E) { s = ei[id]; d = ei[E + id]; }
    else        { s = d = id - E; }
    float e = g_asrc[s] + g_adst[d];
    e = e > 0.f ? e : NEG_SLOPE * e;
    float w = __expf(e);
    g_ebuf[id] = w;
    atomicAdd(&g_denom[d], w);
    atomicAdd(&g_deg[d], 1);
}

// ---------------------------------------------------------------------------
// two-level exclusive scan of degrees
// ---------------------------------------------------------------------------
__global__ void scan_block_kernel(int N) {
    const int tid = threadIdx.x;
    const int i   = blockIdx.x * 1024 + tid;
    __shared__ int warp_sums[32];
    int v = (i < N) ? g_deg[i] : 0;
    int incl = v;
    #pragma unroll
    for (int o = 1; o < 32; o <<= 1) {
        int t = __shfl_up_sync(0xFFFFFFFFu, incl, o);
        if ((tid & 31) >= o) incl += t;
    }
    if ((tid & 31) == 31) warp_sums[tid >> 5] = incl;
    __syncthreads();
    if (tid < 32) {
        int ws = warp_sums[tid];
        #pragma unroll
        for (int o = 1; o < 32; o <<= 1) {
            int t = __shfl_up_sync(0xFFFFFFFFu, ws, o);
            if (tid >= o) ws += t;
        }
        warp_sums[tid] = ws;
    }
    __syncthreads();
    int warp_prefix = (tid >= 32) ? warp_sums[(tid >> 5) - 1] : 0;
    if (i < N) g_off[i] = warp_prefix + incl - v;
    if (tid == 0) g_bsum[blockIdx.x] = warp_sums[31];
}

__global__ void scan_tops_kernel(int nb) {
    const int tid = threadIdx.x;
    __shared__ int warp_sums[32];
    int v = (tid < nb) ? g_bsum[tid] : 0;
    int incl = v;
    #pragma unroll
    for (int o = 1; o < 32; o <<= 1) {
        int t = __shfl_up_sync(0xFFFFFFFFu, incl, o);
        if ((tid & 31) >= o) incl += t;
    }
    if ((tid & 31) == 31) warp_sums[tid >> 5] = incl;
    __syncthreads();
    if (tid < 32) {
        int ws = warp_sums[tid];
        #pragma unroll
        for (int o = 1; o < 32; o <<= 1) {
            int t = __shfl_up_sync(0xFFFFFFFFu, ws, o);
            if (tid >= o) ws += t;
        }
        warp_sums[tid] = ws;
    }
    __syncthreads();
    int warp_prefix = (tid >= 32) ? warp_sums[(tid >> 5) - 1] : 0;
    if (tid < nb) g_bpre[tid] = warp_prefix + incl - v;
}

// ---------------------------------------------------------------------------
// pass_b: CSR scatter of (src, w)
// ---------------------------------------------------------------------------
__global__ void pass_b_kernel(const int* __restrict__ ei, int E, int N) {
    int id = blockIdx.x * blockDim.x + threadIdx.x;
    if (id >= E + N) return;
    int s, d;
    if (id < E) { s = ei[id]; d = ei[E + id]; }
    else        { s = d = id - E; }
    int pos = g_off[d] + g_bpre[d >> 10] + atomicAdd(&g_cursor[d], 1);
    g_csr_src[pos] = s;
    g_csr_w[pos]   = g_ebuf[id];
}

// ---------------------------------------------------------------------------
// gather: atomic-free. One warp per dst node; lane = 4 features.
// ---------------------------------------------------------------------------
__global__ void gather_kernel(const float* __restrict__ bias,
                              float* __restrict__ out, int N) {
    int gt   = blockIdx.x * blockDim.x + threadIdx.x;
    int node = gt >> 5;
    int lane = gt & 31;
    if (node >= N) return;

    float4 acc = *(const float4*)(bias + lane * 4);
    float dinv = 1.f / (g_denom[node] + EPS_A);
    int off = g_off[node] + g_bpre[node >> 10];
    int deg = g_deg[node];

    for (int i = 0; i < deg; i++) {
        int s   = g_csr_src[off + i];
        float a = g_csr_w[off + i] * dinv;
        float4 hv = *(const float4*)(g_h + (size_t)s * F_OUT + lane * 4);
        acc.x += a * hv.x;
        acc.y += a * hv.y;
        acc.z += a * hv.z;
        acc.w += a * hv.w;
    }
    *(float4*)(out + (size_t)node * F_OUT + lane * 4) = acc;
}

// ---------------------------------------------------------------------------
extern "C" void kernel_launch(void* const* d_in, const int* in_sizes, int n_in,
                              void* d_out, int out_size) {
    const float* x       = (const float*)d_in[0];
    const int*   ei      = (const int*)d_in[1];
    const float* W       = (const float*)d_in[2];
    const float* att_src = (const float*)d_in[3];
    const float* att_dst = (const float*)d_in[4];
    const float* bias    = (const float*)d_in[5];
    float*       out     = (float*)d_out;

    const int Fout = in_sizes[3];            // 128
    const int Fin  = in_sizes[2] / Fout;     // 256
    const int N    = in_sizes[0] / Fin;      // 50000
    const int E    = in_sizes[1] / 2;        // 800000
    const int tot  = E + N;
    const int nb   = (N + 1023) / 1024;

    split_w_kernel<<<(F_IN * F_OUT) / 256, 256>>>(W);   // launch 0
    init_denom_kernel<<<(N + 255) / 256, 256>>>(N);     // launch 1
    init_degcur_kernel<<<(N + 255) / 256, 256>>>(N);    // launch 2
    gemm_h_kernel<<<(N + 127) / 128, 256>>>(x, att_src, att_dst, N); // launch 3 (profiled)
    pass_a_kernel<<<(tot + 255) / 256, 256>>>(ei, E, N);
    scan_block_kernel<<<nb, 1024>>>(N);
    scan_tops_kernel<<<1, 1024>>>(nb);
    pass_b_kernel<<<(tot + 255) / 256, 256>>>(ei, E, N);
    gather_kernel<<<((size_t)N * 32 + 255) / 256, 256>>>(bias, out, N);
}

// round 13
// speedup vs baseline: 1.5322x; 1.0724x over previous
#include <cuda_runtime.h>
#include <cuda_bf16.h>
#include <cstdint>

#define F_IN      256
#define F_OUT     128
#define NEG_SLOPE 0.2f
#define EPS_A     1e-16f
#define MAXN      50000
#define MAXE      800000
#define MAXT      (MAXE + MAXN)
#define MAXB      ((MAXN + 1023) / 1024)

// Scratch (device globals: allocation-free kernel_launch)
__device__ float g_h[(size_t)MAXN * F_OUT];   // 25.6 MB
__device__ __nv_bfloat16 g_wt_hi[F_OUT * F_IN];  // W^T hi [128][256]
__device__ __nv_bfloat16 g_wt_lo[F_OUT * F_IN];  // W^T lo
__device__ float g_asrc[MAXN];
__device__ float g_adst[MAXN];
__device__ float g_denom[MAXN];
__device__ float g_ebuf[MAXT];                // per-edge exp weight
__device__ int   g_deg[MAXN];
__device__ int   g_off[MAXN];
__device__ int   g_bsum[MAXB];
__device__ int   g_bpre[MAXB];
__device__ int   g_cursor[MAXN];
__device__ int   g_csr_src[MAXT];
__device__ float g_csr_w[MAXT];

__device__ __forceinline__ uint32_t smem_u32(const void* p) {
    uint32_t a;
    asm("{ .reg .u64 t; cvta.to.shared.u64 t, %1; cvt.u32.u64 %0, t; }"
        : "=r"(a) : "l"(p));
    return a;
}

#define LDSM_X4(r, addr) \
    asm volatile("ldmatrix.sync.aligned.m8n8.x4.shared.b16 {%0,%1,%2,%3}, [%4];" \
        : "=r"((r)[0]), "=r"((r)[1]), "=r"((r)[2]), "=r"((r)[3]) : "r"(addr))
#define LDSM_X2(r, addr) \
    asm volatile("ldmatrix.sync.aligned.m8n8.x2.shared.b16 {%0,%1}, [%2];" \
        : "=r"((r)[0]), "=r"((r)[1]) : "r"(addr))
#define MMA_BF16(c, a, b) \
    asm volatile("mma.sync.aligned.m16n8k16.row.col.f32.bf16.bf16.f32 " \
        "{%0,%1,%2,%3}, {%4,%5,%6,%7}, {%8,%9}, {%0,%1,%2,%3};" \
        : "+f"((c)[0]), "+f"((c)[1]), "+f"((c)[2]), "+f"((c)[3]) \
        : "r"((a)[0]), "r"((a)[1]), "r"((a)[2]), "r"((a)[3]), \
          "r"((b)[0]), "r"((b)[1]))
#define CPA16(dst, src, sz) \
    asm volatile("cp.async.ca.shared.global [%0], [%1], 16, %2;" \
        :: "r"(dst), "l"(src), "r"(sz))
#define CPA_COMMIT() asm volatile("cp.async.commit_group;")
#define CPA_WAIT(n)  asm volatile("cp.async.wait_group %0;" :: "n"(n))

// Dynamic SMEM layout (bytes):
//  [0,16384)      xf32[2][128][16]  fp32 staging (cp.async dst)
//  [16384,28672)  As_hi[2][128][24] bf16
//  [28672,40960)  As_lo[2][128][24]
//  [40960,53248)  Bs_hi[2][128][24]
//  [53248,65536)  Bs_lo[2][128][24]
#define XOFF   0
#define ASH    16384
#define ASL    28672
#define BSH    40960
#define BSL    53248
#define XBUF   8192
#define TBUF   6144
#define GEMM_SMEM 65536

// ---------------------------------------------------------------------------
// Kernel 0: split W [256][128] fp32 -> transposed bf16 hi/lo [128][256]
// ---------------------------------------------------------------------------
__global__ void split_w_kernel(const float* __restrict__ W) {
    int i = blockIdx.x * 256 + threadIdx.x;   // 32768
    int n = i >> 8, k = i & 255;
    float v = W[(size_t)k * F_OUT + n];
    __nv_bfloat16 hi = __float2bfloat16(v);
    float lo = v - __bfloat162float(hi);
    g_wt_hi[n * F_IN + k] = hi;
    g_wt_lo[n * F_IN + k] = __float2bfloat16(lo);
}

// ---------------------------------------------------------------------------
// Kernel (launch 3): h = x @ W via mma.sync bf16 (2-term split, 3 MMA terms),
// cp.async double-buffered pipeline, fused attention dots.
// Per chunk: sync (buffer-reuse guard) -> issue cp(ch+1) -> wait(ch) ->
// convert -> sync -> ldsm+mma. The top sync fixes R12's WAR race (cp.async
// overwrote the buffer slow warps were still ldsm-ing).
// ---------------------------------------------------------------------------
__global__ void __launch_bounds__(256, 2)
gemm_h_kernel(const float* __restrict__ x,
              const float* __restrict__ att_src,
              const float* __restrict__ att_dst, int N) {
    extern __shared__ char sm[];
    const uint32_t base = smem_u32(sm);

    const int tid  = threadIdx.x;
    const int lane = tid & 31;
    const int wid  = tid >> 5;
    const int warpM = wid & 3;
    const int warpN = wid >> 2;
    const int bm = blockIdx.x * 128;

    float acc[2][8][4];
    #pragma unroll
    for (int m = 0; m < 2; m++)
        #pragma unroll
        for (int n = 0; n < 8; n++)
            #pragma unroll
            for (int q = 0; q < 4; q++) acc[m][n][q] = 0.f;

    // ldmatrix lane offsets (row stride 48B)
    const uint32_t aoff = (uint32_t)(warpM * 32 + (lane & 15)) * 48u
                        + (uint32_t)(lane >> 4) * 16u;
    const uint32_t boff = (uint32_t)(warpN * 64 + (lane & 7)) * 48u
                        + (uint32_t)((lane >> 3) & 1) * 16u;

    // Staging indices
    const int xr0 = tid >> 2,          xk0 = (tid & 3) * 4;
    const int xr1 = (tid + 256) >> 2,  xk1 = ((tid + 256) & 3) * 4;
    const int wn = tid >> 1, wh8 = (tid & 1) * 8;
    const int x0ok = (bm + xr0 < N) ? 16 : 0;
    const int x1ok = (bm + xr1 < N) ? 16 : 0;
    const float* xs0 = x + (size_t)(bm + xr0) * F_IN + xk0;
    const float* xs1 = x + (size_t)(bm + xr1) * F_IN + xk1;
    const __nv_bfloat16* ws_hi = g_wt_hi + (size_t)wn * F_IN + wh8;
    const __nv_bfloat16* ws_lo = g_wt_lo + (size_t)wn * F_IN + wh8;
    const uint32_t xdst0 = base + XOFF + (uint32_t)(xr0 * 16 + xk0) * 4u;
    const uint32_t xdst1 = base + XOFF + (uint32_t)(xr1 * 16 + xk1) * 4u;
    const uint32_t bdst_h = base + BSH + (uint32_t)(wn * 48 + (tid & 1) * 16);
    const uint32_t bdst_l = base + BSL + (uint32_t)(wn * 48 + (tid & 1) * 16);

#define ISSUE_CP(kk_, buf_) do {                                      \
    CPA16(xdst0 + (buf_) * XBUF, xs0 + (kk_), x0ok);                  \
    CPA16(xdst1 + (buf_) * XBUF, xs1 + (kk_), x1ok);                  \
    CPA16(bdst_h + (buf_) * TBUF, ws_hi + (kk_), 16);                 \
    CPA16(bdst_l + (buf_) * TBUF, ws_lo + (kk_), 16);                 \
} while (0)

    ISSUE_CP(0, 0);
    CPA_COMMIT();

    for (int ch = 0; ch < 16; ch++) {
        const int buf = ch & 1;
        // Guard: all warps done reading buf^1 (chunk ch-1) before cp.async
        // overwrites it.
        __syncthreads();
        if (ch < 15) {
            ISSUE_CP((ch + 1) * 16, buf ^ 1);
            CPA_COMMIT();
            CPA_WAIT(1);        // group(ch) complete (own-thread data)
        } else {
            CPA_WAIT(0);
        }

        // Convert x fp32 (own smem words) -> bf16 hi/lo tiles
        {
            const float4 v0 = *(const float4*)(sm + XOFF + buf * XBUF
                                               + (xr0 * 16 + xk0) * 4);
            const float4 v1 = *(const float4*)(sm + XOFF + buf * XBUF
                                               + (xr1 * 16 + xk1) * 4);
            char* ah = sm + ASH + buf * TBUF;
            char* al = sm + ASL + buf * TBUF;
            __nv_bfloat162 h0 = __floats2bfloat162_rn(v0.x, v0.y);
            __nv_bfloat162 h1 = __floats2bfloat162_rn(v0.z, v0.w);
            float2 f0 = __bfloat1622float2(h0), f1 = __bfloat1622float2(h1);
            *(uint2*)(ah + xr0 * 48 + xk0 * 2) =
                make_uint2(*(uint32_t*)&h0, *(uint32_t*)&h1);
            __nv_bfloat162 l0 = __floats2bfloat162_rn(v0.x - f0.x, v0.y - f0.y);
            __nv_bfloat162 l1 = __floats2bfloat162_rn(v0.z - f1.x, v0.w - f1.y);
            *(uint2*)(al + xr0 * 48 + xk0 * 2) =
                make_uint2(*(uint32_t*)&l0, *(uint32_t*)&l1);
            h0 = __floats2bfloat162_rn(v1.x, v1.y);
            h1 = __floats2bfloat162_rn(v1.z, v1.w);
            f0 = __bfloat1622float2(h0); f1 = __bfloat1622float2(h1);
            *(uint2*)(ah + xr1 * 48 + xk1 * 2) =
                make_uint2(*(uint32_t*)&h0, *(uint32_t*)&h1);
            l0 = __floats2bfloat162_rn(v1.x - f0.x, v1.y - f0.y);
            l1 = __floats2bfloat162_rn(v1.z - f1.x, v1.w - f1.y);
            *(uint2*)(al + xr1 * 48 + xk1 * 2) =
                make_uint2(*(uint32_t*)&l0, *(uint32_t*)&l1);
        }
        __syncthreads();

        const uint32_t ash = base + ASH + buf * TBUF;
        const uint32_t asl = base + ASL + buf * TBUF;
        const uint32_t bsh = base + BSH + buf * TBUF;
        const uint32_t bsl = base + BSL + buf * TBUF;

        uint32_t ahf[2][4], alf[2][4];
        LDSM_X4(ahf[0], ash + aoff);
        LDSM_X4(ahf[1], ash + aoff + 16u * 48u);
        LDSM_X4(alf[0], asl + aoff);
        LDSM_X4(alf[1], asl + aoff + 16u * 48u);

        #pragma unroll
        for (int nt = 0; nt < 8; nt++) {
            uint32_t bh[2], bl[2];
            LDSM_X2(bh, bsh + boff + (uint32_t)nt * 384u);
            LDSM_X2(bl, bsl + boff + (uint32_t)nt * 384u);
            #pragma unroll
            for (int mt = 0; mt < 2; mt++) {
                MMA_BF16(acc[mt][nt], ahf[mt], bh);
                MMA_BF16(acc[mt][nt], ahf[mt], bl);
                MMA_BF16(acc[mt][nt], alf[mt], bh);
            }
        }
    }

    // Epilogue: store h + fused attention dots
    const int r0 = bm + warpM * 32 + (lane >> 2);
    const int cbase = warpN * 64 + (lane & 3) * 2;
    float ps[2][2], pd[2][2];
    #pragma unroll
    for (int mt = 0; mt < 2; mt++)
        ps[mt][0] = ps[mt][1] = pd[mt][0] = pd[mt][1] = 0.f;

    #pragma unroll
    for (int mt = 0; mt < 2; mt++) {
        int ra = r0 + mt * 16, rb = ra + 8;
        #pragma unroll
        for (int nt = 0; nt < 8; nt++) {
            int c = cbase + nt * 8;
            if (ra < N)
                *(float2*)(g_h + (size_t)ra * F_OUT + c) =
                    make_float2(acc[mt][nt][0], acc[mt][nt][1]);
            if (rb < N)
                *(float2*)(g_h + (size_t)rb * F_OUT + c) =
                    make_float2(acc[mt][nt][2], acc[mt][nt][3]);
            float2 sv = *(const float2*)(att_src + c);
            float2 dv = *(const float2*)(att_dst + c);
            ps[mt][0] += acc[mt][nt][0] * sv.x + acc[mt][nt][1] * sv.y;
            ps[mt][1] += acc[mt][nt][2] * sv.x + acc[mt][nt][3] * sv.y;
            pd[mt][0] += acc[mt][nt][0] * dv.x + acc[mt][nt][1] * dv.y;
            pd[mt][1] += acc[mt][nt][2] * dv.x + acc[mt][nt][3] * dv.y;
        }
    }
    #pragma unroll
    for (int mt = 0; mt < 2; mt++) {
        #pragma unroll
        for (int h = 0; h < 2; h++) {
            float s = ps[mt][h], d = pd[mt][h];
            s += __shfl_xor_sync(0xFFFFFFFFu, s, 1);
            s += __shfl_xor_sync(0xFFFFFFFFu, s, 2);
            d += __shfl_xor_sync(0xFFFFFFFFu, d, 1);
            d += __shfl_xor_sync(0xFFFFFFFFu, d, 2);
            int row = r0 + mt * 16 + h * 8;
            if ((lane & 3) == 0 && row < N) {
                atomicAdd(&g_asrc[row], s);
                atomicAdd(&g_adst[row], d);
            }
        }
    }
}

// ---------------------------------------------------------------------------
// Init (2 kernels; keeps gemm at launch index 3 for the profiler)
// ---------------------------------------------------------------------------
__global__ void init_denom_kernel(int N) {
    int i = blockIdx.x * blockDim.x + threadIdx.x;
    if (i < N) { g_denom[i] = 0.f; g_asrc[i] = 0.f; g_adst[i] = 0.f; }
}
__global__ void init_degcur_kernel(int N) {
    int i = blockIdx.x * blockDim.x + threadIdx.x;
    if (i < N) { g_deg[i] = 0; g_cursor[i] = 0; }
}

// ---------------------------------------------------------------------------
// pass_a: fused logits -> exp -> denom + degree count (no max-shift: logits
// bounded ~|10|, exp safe in fp32; alpha mathematically identical.)
// ---------------------------------------------------------------------------
__global__ void pass_a_kernel(const int* __restrict__ ei, int E, int N) {
    int id = blockIdx.x * blockDim.x + threadIdx.x;
    if (id >= E + N) return;
    int s, d;
    if (id < E) { s = ei[id]; d = ei[E + id]; }
    else        { s = d = id - E; }
    float e = g_asrc[s] + g_adst[d];
    e = e > 0.f ? e : NEG_SLOPE * e;
    float w = __expf(e);
    g_ebuf[id] = w;
    atomicAdd(&g_denom[d], w);
    atomicAdd(&g_deg[d], 1);
}

// ---------------------------------------------------------------------------
// two-level exclusive scan of degrees
// ---------------------------------------------------------------------------
__global__ void scan_block_kernel(int N) {
    const int tid = threadIdx.x;
    const int i   = blockIdx.x * 1024 + tid;
    __shared__ int warp_sums[32];
    int v = (i < N) ? g_deg[i] : 0;
    int incl = v;
    #pragma unroll
    for (int o = 1; o < 32; o <<= 1) {
        int t = __shfl_up_sync(0xFFFFFFFFu, incl, o);
        if ((tid & 31) >= o) incl += t;
    }
    if ((tid & 31) == 31) warp_sums[tid >> 5] = incl;
    __syncthreads();
    if (tid < 32) {
        int ws = warp_sums[tid];
        #pragma unroll
        for (int o = 1; o < 32; o <<= 1) {
            int t = __shfl_up_sync(0xFFFFFFFFu, ws, o);
            if (tid >= o) ws += t;
        }
        warp_sums[tid] = ws;
    }
    __syncthreads();
    int warp_prefix = (tid >= 32) ? warp_sums[(tid >> 5) - 1] : 0;
    if (i < N) g_off[i] = warp_prefix + incl - v;
    if (tid == 0) g_bsum[blockIdx.x] = warp_sums[31];
}

__global__ void scan_tops_kernel(int nb) {
    const int tid = threadIdx.x;
    __shared__ int warp_sums[32];
    int v = (tid < nb) ? g_bsum[tid] : 0;
    int incl = v;
    #pragma unroll
    for (int o = 1; o < 32; o <<= 1) {
        int t = __shfl_up_sync(0xFFFFFFFFu, incl, o);
        if ((tid & 31) >= o) incl += t;
    }
    if ((tid & 31) == 31) warp_sums[tid >> 5] = incl;
    __syncthreads();
    if (tid < 32) {
        int ws = warp_sums[tid];
        #pragma unroll
        for (int o = 1; o < 32; o <<= 1) {
            int t = __shfl_up_sync(0xFFFFFFFFu, ws, o);
            if (tid >= o) ws += t;
        }
        warp_sums[tid] = ws;
    }
    __syncthreads();
    int warp_prefix = (tid >= 32) ? warp_sums[(tid >> 5) - 1] : 0;
    if (tid < nb) g_bpre[tid] = warp_prefix + incl - v;
}

// ---------------------------------------------------------------------------
// pass_b: CSR scatter of (src, w)
// ---------------------------------------------------------------------------
__global__ void pass_b_kernel(const int* __restrict__ ei, int E, int N) {
    int id = blockIdx.x * blockDim.x + threadIdx.x;
    if (id >= E + N) return;
    int s, d;
    if (id < E) { s = ei[id]; d = ei[E + id]; }
    else        { s = d = id - E; }
    int pos = g_off[d] + g_bpre[d >> 10] + atomicAdd(&g_cursor[d], 1);
    g_csr_src[pos] = s;
    g_csr_w[pos]   = g_ebuf[id];
}

// ---------------------------------------------------------------------------
// gather: atomic-free. One warp per dst node; lane = 4 features.
// ---------------------------------------------------------------------------
__global__ void gather_kernel(const float* __restrict__ bias,
                              float* __restrict__ out, int N) {
    int gt   = blockIdx.x * blockDim.x + threadIdx.x;
    int node = gt >> 5;
    int lane = gt & 31;
    if (node >= N) return;

    float4 acc = *(const float4*)(bias + lane * 4);
    float dinv = 1.f / (g_denom[node] + EPS_A);
    int off = g_off[node] + g_bpre[node >> 10];
    int deg = g_deg[node];

    for (int i = 0; i < deg; i++) {
        int s   = g_csr_src[off + i];
        float a = g_csr_w[off + i] * dinv;
        float4 hv = *(const float4*)(g_h + (size_t)s * F_OUT + lane * 4);
        acc.x += a * hv.x;
        acc.y += a * hv.y;
        acc.z += a * hv.z;
        acc.w += a * hv.w;
    }
    *(float4*)(out + (size_t)node * F_OUT + lane * 4) = acc;
}

// ---------------------------------------------------------------------------
extern "C" void kernel_launch(void* const* d_in, const int* in_sizes, int n_in,
                              void* d_out, int out_size) {
    const float* x       = (const float*)d_in[0];
    const int*   ei      = (const int*)d_in[1];
    const float* W       = (const float*)d_in[2];
    const float* att_src = (const float*)d_in[3];
    const float* att_dst = (const float*)d_in[4];
    const float* bias    = (const float*)d_in[5];
    float*       out     = (float*)d_out;

    const int Fout = in_sizes[3];            // 128
    const int Fin  = in_sizes[2] / Fout;     // 256
    const int N    = in_sizes[0] / Fin;      // 50000
    const int E    = in_sizes[1] / 2;        // 800000
    const int tot  = E + N;
    const int nb   = (N + 1023) / 1024;

    cudaFuncSetAttribute(gemm_h_kernel,
                         cudaFuncAttributeMaxDynamicSharedMemorySize,
                         GEMM_SMEM);

    split_w_kernel<<<(F_IN * F_OUT) / 256, 256>>>(W);   // launch 0
    init_denom_kernel<<<(N + 255) / 256, 256>>>(N);     // launch 1
    init_degcur_kernel<<<(N + 255) / 256, 256>>>(N);    // launch 2
    gemm_h_kernel<<<(N + 127) / 128, 256, GEMM_SMEM>>>(x, att_src, att_dst, N); // launch 3
    pass_a_kernel<<<(tot + 255) / 256, 256>>>(ei, E, N);
    scan_block_kernel<<<nb, 1024>>>(N);
    scan_tops_kernel<<<1, 1024>>>(nb);
    pass_b_kernel<<<(tot + 255) / 256, 256>>>(ei, E, N);
    gather_kernel<<<((size_t)N * 32 + 255) / 256, 256>>>(bias, out, N);
}

// round 14
// speedup vs baseline: 1.5560x; 1.0155x over previous
#include <cuda_runtime.h>
#include <cuda_bf16.h>
#include <cstdint>

#define F_IN      256
#define F_OUT     128
#define NEG_SLOPE 0.2f
#define EPS_A     1e-16f
#define MAXN      50000
#define MAXE      800000
#define MAXT      (MAXE + MAXN)
#define MAXB      ((MAXN + 1023) / 1024)

// Scratch (device globals: allocation-free kernel_launch)
__device__ float g_h[(size_t)MAXN * F_OUT];   // 25.6 MB
__device__ __nv_bfloat16 g_wt_hi[F_OUT * F_IN];  // W^T hi [128][256]
__device__ __nv_bfloat16 g_wt_lo[F_OUT * F_IN];  // W^T lo
__device__ float g_asrc[MAXN];
__device__ float g_adst[MAXN];
__device__ float g_denom[MAXN];
__device__ float g_ebuf[MAXT];                // per-edge exp weight
__device__ int   g_deg[MAXN];
__device__ int   g_off[MAXN];
__device__ int   g_bsum[MAXB];
__device__ int   g_bpre[MAXB];
__device__ int   g_cursor[MAXN];
__device__ int   g_csr_src[MAXT];
__device__ float g_csr_w[MAXT];

__device__ __forceinline__ uint32_t smem_u32(const void* p) {
    uint32_t a;
    asm("{ .reg .u64 t; cvta.to.shared.u64 t, %1; cvt.u32.u64 %0, t; }"
        : "=r"(a) : "l"(p));
    return a;
}

#define LDSM_X4(r, addr) \
    asm volatile("ldmatrix.sync.aligned.m8n8.x4.shared.b16 {%0,%1,%2,%3}, [%4];" \
        : "=r"((r)[0]), "=r"((r)[1]), "=r"((r)[2]), "=r"((r)[3]) : "r"(addr))
#define MMA_BF16(c, a, b) \
    asm volatile("mma.sync.aligned.m16n8k16.row.col.f32.bf16.bf16.f32 " \
        "{%0,%1,%2,%3}, {%4,%5,%6,%7}, {%8,%9}, {%0,%1,%2,%3};" \
        : "+f"((c)[0]), "+f"((c)[1]), "+f"((c)[2]), "+f"((c)[3]) \
        : "r"((a)[0]), "r"((a)[1]), "r"((a)[2]), "r"((a)[3]), \
          "r"((b)[0]), "r"((b)[1]))
#define CPA16(dst, src, sz) \
    asm volatile("cp.async.ca.shared.global [%0], [%1], 16, %2;" \
        :: "r"(dst), "l"(src), "r"(sz))
#define CPA_COMMIT() asm volatile("cp.async.commit_group;")
#define CPA_WAIT(n)  asm volatile("cp.async.wait_group %0;" :: "n"(n))

// Dynamic SMEM layout (bytes): see R13
#define XOFF   0
#define ASH    16384
#define ASL    28672
#define BSH    40960
#define BSL    53248
#define XBUF   8192
#define TBUF   6144
#define GEMM_SMEM 65536

// ---------------------------------------------------------------------------
// Kernel 0: split W [256][128] fp32 -> transposed bf16 hi/lo [128][256]
// ---------------------------------------------------------------------------
__global__ void split_w_kernel(const float* __restrict__ W) {
    int i = blockIdx.x * 256 + threadIdx.x;   // 32768
    int n = i >> 8, k = i & 255;
    float v = W[(size_t)k * F_OUT + n];
    __nv_bfloat16 hi = __float2bfloat16(v);
    float lo = v - __bfloat162float(hi);
    g_wt_hi[n * F_IN + k] = hi;
    g_wt_lo[n * F_IN + k] = __float2bfloat16(lo);
}

// ---------------------------------------------------------------------------
// Kernel (launch 3): h = x @ W via mma.sync bf16 (2-term split, 3 MMA terms),
// cp.async double-buffered pipeline, fused attention dots.
// B fragments via ldmatrix.x4 (nt pairs); MMAs issued term-major so each
// accumulator's RAW reuse distance is 4 independent MMAs (asm volatile
// preserves order; the R13 ordering serialized 3 MMAs on one acc).
// ---------------------------------------------------------------------------
__global__ void __launch_bounds__(256, 2)
gemm_h_kernel(const float* __restrict__ x,
              const float* __restrict__ att_src,
              const float* __restrict__ att_dst, int N) {
    extern __shared__ char sm[];
    const uint32_t base = smem_u32(sm);

    const int tid  = threadIdx.x;
    const int lane = tid & 31;
    const int wid  = tid >> 5;
    const int warpM = wid & 3;
    const int warpN = wid >> 2;
    const int bm = blockIdx.x * 128;

    float acc[2][8][4];
    #pragma unroll
    for (int m = 0; m < 2; m++)
        #pragma unroll
        for (int n = 0; n < 8; n++)
            #pragma unroll
            for (int q = 0; q < 4; q++) acc[m][n][q] = 0.f;

    // ldmatrix lane offsets (row stride 48B)
    const uint32_t aoff = (uint32_t)(warpM * 32 + (lane & 15)) * 48u
                        + (uint32_t)(lane >> 4) * 16u;
    // B x4: lanes 0-15 -> nt even (rows +0..7), lanes 16-31 -> nt odd (+8);
    // (lane>>3)&1 selects the 16B k-half within each group.
    const uint32_t boff4 = (uint32_t)(warpN * 64 + (lane & 7) + (lane >> 4) * 8) * 48u
                         + (uint32_t)((lane >> 3) & 1) * 16u;

    // Staging indices
    const int xr0 = tid >> 2,          xk0 = (tid & 3) * 4;
    const int xr1 = (tid + 256) >> 2,  xk1 = ((tid + 256) & 3) * 4;
    const int wn = tid >> 1, wh8 = (tid & 1) * 8;
    const int x0ok = (bm + xr0 < N) ? 16 : 0;
    const int x1ok = (bm + xr1 < N) ? 16 : 0;
    const float* xs0 = x + (size_t)(bm + xr0) * F_IN + xk0;
    const float* xs1 = x + (size_t)(bm + xr1) * F_IN + xk1;
    const __nv_bfloat16* ws_hi = g_wt_hi + (size_t)wn * F_IN + wh8;
    const __nv_bfloat16* ws_lo = g_wt_lo + (size_t)wn * F_IN + wh8;
    const uint32_t xdst0 = base + XOFF + (uint32_t)(xr0 * 16 + xk0) * 4u;
    const uint32_t xdst1 = base + XOFF + (uint32_t)(xr1 * 16 + xk1) * 4u;
    const uint32_t bdst_h = base + BSH + (uint32_t)(wn * 48 + (tid & 1) * 16);
    const uint32_t bdst_l = base + BSL + (uint32_t)(wn * 48 + (tid & 1) * 16);

#define ISSUE_CP(kk_, buf_) do {                                      \
    CPA16(xdst0 + (buf_) * XBUF, xs0 + (kk_), x0ok);                  \
    CPA16(xdst1 + (buf_) * XBUF, xs1 + (kk_), x1ok);                  \
    CPA16(bdst_h + (buf_) * TBUF, ws_hi + (kk_), 16);                 \
    CPA16(bdst_l + (buf_) * TBUF, ws_lo + (kk_), 16);                 \
} while (0)

    ISSUE_CP(0, 0);
    CPA_COMMIT();

    for (int ch = 0; ch < 16; ch++) {
        const int buf = ch & 1;
        // Guard: all warps done reading buf^1 before cp.async overwrites it.
        __syncthreads();
        if (ch < 15) {
            ISSUE_CP((ch + 1) * 16, buf ^ 1);
            CPA_COMMIT();
            CPA_WAIT(1);
        } else {
            CPA_WAIT(0);
        }

        // Convert x fp32 (own smem words) -> bf16 hi/lo tiles
        {
            const float4 v0 = *(const float4*)(sm + XOFF + buf * XBUF
                                               + (xr0 * 16 + xk0) * 4);
            const float4 v1 = *(const float4*)(sm + XOFF + buf * XBUF
                                               + (xr1 * 16 + xk1) * 4);
            char* ah = sm + ASH + buf * TBUF;
            char* al = sm + ASL + buf * TBUF;
            __nv_bfloat162 h0 = __floats2bfloat162_rn(v0.x, v0.y);
            __nv_bfloat162 h1 = __floats2bfloat162_rn(v0.z, v0.w);
            float2 f0 = __bfloat1622float2(h0), f1 = __bfloat1622float2(h1);
            *(uint2*)(ah + xr0 * 48 + xk0 * 2) =
                make_uint2(*(uint32_t*)&h0, *(uint32_t*)&h1);
            __nv_bfloat162 l0 = __floats2bfloat162_rn(v0.x - f0.x, v0.y - f0.y);
            __nv_bfloat162 l1 = __floats2bfloat162_rn(v0.z - f1.x, v0.w - f1.y);
            *(uint2*)(al + xr0 * 48 + xk0 * 2) =
                make_uint2(*(uint32_t*)&l0, *(uint32_t*)&l1);
            h0 = __floats2bfloat162_rn(v1.x, v1.y);
            h1 = __floats2bfloat162_rn(v1.z, v1.w);
            f0 = __bfloat1622float2(h0); f1 = __bfloat1622float2(h1);
            *(uint2*)(ah + xr1 * 48 + xk1 * 2) =
                make_uint2(*(uint32_t*)&h0, *(uint32_t*)&h1);
            l0 = __floats2bfloat162_rn(v1.x - f0.x, v1.y - f0.y);
            l1 = __floats2bfloat162_rn(v1.z - f1.x, v1.w - f1.y);
            *(uint2*)(al + xr1 * 48 + xk1 * 2) =
                make_uint2(*(uint32_t*)&l0, *(uint32_t*)&l1);
        }
        __syncthreads();

        const uint32_t ash = base + ASH + buf * TBUF;
        const uint32_t asl = base + ASL + buf * TBUF;
        const uint32_t bsh = base + BSH + buf * TBUF;
        const uint32_t bsl = base + BSL + buf * TBUF;

        uint32_t ahf[2][4], alf[2][4];
        LDSM_X4(ahf[0], ash + aoff);
        LDSM_X4(ahf[1], ash + aoff + 16u * 48u);
        LDSM_X4(alf[0], asl + aoff);
        LDSM_X4(alf[1], asl + aoff + 16u * 48u);

        #pragma unroll
        for (int ntp = 0; ntp < 4; ntp++) {
            const int n0 = ntp * 2, n1 = ntp * 2 + 1;
            uint32_t bh4[4], bl4[4];
            LDSM_X4(bh4, bsh + boff4 + (uint32_t)ntp * 768u);
            LDSM_X4(bl4, bsl + boff4 + (uint32_t)ntp * 768u);
            // term-major: 4 independent MMAs between acc reuses
            MMA_BF16(acc[0][n0], ahf[0], bh4);
            MMA_BF16(acc[1][n0], ahf[1], bh4);
            MMA_BF16(acc[0][n1], ahf[0], bh4 + 2);
            MMA_BF16(acc[1][n1], ahf[1], bh4 + 2);
            MMA_BF16(acc[0][n0], ahf[0], bl4);
            MMA_BF16(acc[1][n0], ahf[1], bl4);
            MMA_BF16(acc[0][n1], ahf[0], bl4 + 2);
            MMA_BF16(acc[1][n1], ahf[1], bl4 + 2);
            MMA_BF16(acc[0][n0], alf[0], bh4);
            MMA_BF16(acc[1][n0], alf[1], bh4);
            MMA_BF16(acc[0][n1], alf[0], bh4 + 2);
            MMA_BF16(acc[1][n1], alf[1], bh4 + 2);
        }
    }

    // Epilogue: store h + fused attention dots
    const int r0 = bm + warpM * 32 + (lane >> 2);
    const int cbase = warpN * 64 + (lane & 3) * 2;
    float ps[2][2], pd[2][2];
    #pragma unroll
    for (int mt = 0; mt < 2; mt++)
        ps[mt][0] = ps[mt][1] = pd[mt][0] = pd[mt][1] = 0.f;

    #pragma unroll
    for (int mt = 0; mt < 2; mt++) {
        int ra = r0 + mt * 16, rb = ra + 8;
        #pragma unroll
        for (int nt = 0; nt < 8; nt++) {
            int c = cbase + nt * 8;
            if (ra < N)
                *(float2*)(g_h + (size_t)ra * F_OUT + c) =
                    make_float2(acc[mt][nt][0], acc[mt][nt][1]);
            if (rb < N)
                *(float2*)(g_h + (size_t)rb * F_OUT + c) =
                    make_float2(acc[mt][nt][2], acc[mt][nt][3]);
            float2 sv = *(const float2*)(att_src + c);
            float2 dv = *(const float2*)(att_dst + c);
            ps[mt][0] += acc[mt][nt][0] * sv.x + acc[mt][nt][1] * sv.y;
            ps[mt][1] += acc[mt][nt][2] * sv.x + acc[mt][nt][3] * sv.y;
            pd[mt][0] += acc[mt][nt][0] * dv.x + acc[mt][nt][1] * dv.y;
            pd[mt][1] += acc[mt][nt][2] * dv.x + acc[mt][nt][3] * dv.y;
        }
    }
    #pragma unroll
    for (int mt = 0; mt < 2; mt++) {
        #pragma unroll
        for (int h = 0; h < 2; h++) {
            float s = ps[mt][h], d = pd[mt][h];
            s += __shfl_xor_sync(0xFFFFFFFFu, s, 1);
            s += __shfl_xor_sync(0xFFFFFFFFu, s, 2);
            d += __shfl_xor_sync(0xFFFFFFFFu, d, 1);
            d += __shfl_xor_sync(0xFFFFFFFFu, d, 2);
            int row = r0 + mt * 16 + h * 8;
            if ((lane & 3) == 0 && row < N) {
                atomicAdd(&g_asrc[row], s);
                atomicAdd(&g_adst[row], d);
            }
        }
    }
}

// ---------------------------------------------------------------------------
// Init (2 kernels; keeps gemm at launch index 3 for the profiler)
// ---------------------------------------------------------------------------
__global__ void init_denom_kernel(int N) {
    int i = blockIdx.x * blockDim.x + threadIdx.x;
    if (i < N) { g_denom[i] = 0.f; g_asrc[i] = 0.f; g_adst[i] = 0.f; }
}
__global__ void init_degcur_kernel(int N) {
    int i = blockIdx.x * blockDim.x + threadIdx.x;
    if (i < N) { g_deg[i] = 0; g_cursor[i] = 0; }
}

// ---------------------------------------------------------------------------
// pass_a: fused logits -> exp -> denom + degree count (no max-shift: logits
// bounded ~|10|, exp safe in fp32; alpha mathematically identical.)
// ---------------------------------------------------------------------------
__global__ void pass_a_kernel(const int* __restrict__ ei, int E, int N) {
    int id = blockIdx.x * blockDim.x + threadIdx.x;
    if (id >= E + N) return;
    int s, d;
    if (id < E) { s = ei[id]; d = ei[E + id]; }
    else        { s = d = id - E; }
    float e = g_asrc[s] + g_adst[d];
    e = e > 0.f ? e : NEG_SLOPE * e;
    float w = __expf(e);
    g_ebuf[id] = w;
    atomicAdd(&g_denom[d], w);
    atomicAdd(&g_deg[d], 1);
}

// ---------------------------------------------------------------------------
// two-level exclusive scan of degrees
// ---------------------------------------------------------------------------
__global__ void scan_block_kernel(int N) {
    const int tid = threadIdx.x;
    const int i   = blockIdx.x * 1024 + tid;
    __shared__ int warp_sums[32];
    int v = (i < N) ? g_deg[i] : 0;
    int incl = v;
    #pragma unroll
    for (int o = 1; o < 32; o <<= 1) {
        int t = __shfl_up_sync(0xFFFFFFFFu, incl, o);
        if ((tid & 31) >= o) incl += t;
    }
    if ((tid & 31) == 31) warp_sums[tid >> 5] = incl;
    __syncthreads();
    if (tid < 32) {
        int ws = warp_sums[tid];
        #pragma unroll
        for (int o = 1; o < 32; o <<= 1) {
            int t = __shfl_up_sync(0xFFFFFFFFu, ws, o);
            if (tid >= o) ws += t;
        }
        warp_sums[tid] = ws;
    }
    __syncthreads();
    int warp_prefix = (tid >= 32) ? warp_sums[(tid >> 5) - 1] : 0;
    if (i < N) g_off[i] = warp_prefix + incl - v;
    if (tid == 0) g_bsum[blockIdx.x] = warp_sums[31];
}

__global__ void scan_tops_kernel(int nb) {
    const int tid = threadIdx.x;
    __shared__ int warp_sums[32];
    int v = (tid < nb) ? g_bsum[tid] : 0;
    int incl = v;
    #pragma unroll
    for (int o = 1; o < 32; o <<= 1) {
        int t = __shfl_up_sync(0xFFFFFFFFu, incl, o);
        if ((tid & 31) >= o) incl += t;
    }
    if ((tid & 31) == 31) warp_sums[tid >> 5] = incl;
    __syncthreads();
    if (tid < 32) {
        int ws = warp_sums[tid];
        #pragma unroll
        for (int o = 1; o < 32; o <<= 1) {
            int t = __shfl_up_sync(0xFFFFFFFFu, ws, o);
            if (tid >= o) ws += t;
        }
        warp_sums[tid] = ws;
    }
    __syncthreads();
    int warp_prefix = (tid >= 32) ? warp_sums[(tid >> 5) - 1] : 0;
    if (tid < nb) g_bpre[tid] = warp_prefix + incl - v;
}

// ---------------------------------------------------------------------------
// pass_b: CSR scatter of (src, w)
// ---------------------------------------------------------------------------
__global__ void pass_b_kernel(const int* __restrict__ ei, int E, int N) {
    int id = blockIdx.x * blockDim.x + threadIdx.x;
    if (id >= E + N) return;
    int s, d;
    if (id < E) { s = ei[id]; d = ei[E + id]; }
    else        { s = d = id - E; }
    int pos = g_off[d] + g_bpre[d >> 10] + atomicAdd(&g_cursor[d], 1);
    g_csr_src[pos] = s;
    g_csr_w[pos]   = g_ebuf[id];
}

// ---------------------------------------------------------------------------
// gather: atomic-free. One warp per dst node; lane = 4 features.
// ---------------------------------------------------------------------------
__global__ void gather_kernel(const float* __restrict__ bias,
                              float* __restrict__ out, int N) {
    int gt   = blockIdx.x * blockDim.x + threadIdx.x;
    int node = gt >> 5;
    int lane = gt & 31;
    if (node >= N) return;

    float4 acc = *(const float4*)(bias + lane * 4);
    float dinv = 1.f / (g_denom[node] + EPS_A);
    int off = g_off[node] + g_bpre[node >> 10];
    int deg = g_deg[node];

    for (int i = 0; i < deg; i++) {
        int s   = g_csr_src[off + i];
        float a = g_csr_w[off + i] * dinv;
        float4 hv = *(const float4*)(g_h + (size_t)s * F_OUT + lane * 4);
        acc.x += a * hv.x;
        acc.y += a * hv.y;
        acc.z += a * hv.z;
        acc.w += a * hv.w;
    }
    *(float4*)(out + (size_t)node * F_OUT + lane * 4) = acc;
}

// ---------------------------------------------------------------------------
extern "C" void kernel_launch(void* const* d_in, const int* in_sizes, int n_in,
                              void* d_out, int out_size) {
    const float* x       = (const float*)d_in[0];
    const int*   ei      = (const int*)d_in[1];
    const float* W       = (const float*)d_in[2];
    const float* att_src = (const float*)d_in[3];
    const float* att_dst = (const float*)d_in[4];
    const float* bias    = (const float*)d_in[5];
    float*       out     = (float*)d_out;

    const int Fout = in_sizes[3];            // 128
    const int Fin  = in_sizes[2] / Fout;     // 256
    const int N    = in_sizes[0] / Fin;      // 50000
    const int E    = in_sizes[1] / 2;        // 800000
    const int tot  = E + N;
    const int nb   = (N + 1023) / 1024;

    cudaFuncSetAttribute(gemm_h_kernel,
                         cudaFuncAttributeMaxDynamicSharedMemorySize,
                         GEMM_SMEM);

    split_w_kernel<<<(F_IN * F_OUT) / 256, 256>>>(W);   // launch 0
    init_denom_kernel<<<(N + 255) / 256, 256>>>(N);     // launch 1
    init_degcur_kernel<<<(N + 255) / 256, 256>>>(N);    // launch 2
    gemm_h_kernel<<<(N + 127) / 128, 256, GEMM_SMEM>>>(x, att_src, att_dst, N); // launch 3
    pass_a_kernel<<<(tot + 255) / 256, 256>>>(ei, E, N);
    scan_block_kernel<<<nb, 1024>>>(N);
    scan_tops_kernel<<<1, 1024>>>(nb);
    pass_b_kernel<<<(tot + 255) / 256, 256>>>(ei, E, N);
    gather_kernel<<<((size_t)N * 32 + 255) / 256, 256>>>(bias, out, N);
}

// round 15
// speedup vs baseline: 1.6022x; 1.0297x over previous
#include <cuda_runtime.h>
#include <cuda_bf16.h>
#include <cstdint>

#define F_IN      256
#define F_OUT     128
#define NEG_SLOPE 0.2f
#define EPS_A     1e-16f
#define MAXN      50000
#define MAXE      800000
#define MAXT      (MAXE + MAXN)
#define MAXB      ((MAXN + 1023) / 1024)

// Scratch (device globals: allocation-free kernel_launch)
__device__ float g_h[(size_t)MAXN * F_OUT];   // 25.6 MB
__device__ __nv_bfloat16 g_wt_hi[F_OUT * F_IN];  // W^T hi [128][256]
__device__ __nv_bfloat16 g_wt_lo[F_OUT * F_IN];  // W^T lo
__device__ float g_asrc[MAXN];
__device__ float g_adst[MAXN];
__device__ float g_denom[MAXN];
__device__ int   g_deg[MAXN];
__device__ int   g_off[MAXN];
__device__ int   g_bsum[MAXB];
__device__ int   g_bpre[MAXB];
__device__ int   g_cursor[MAXN];
__device__ int   g_csr_src[MAXT];
__device__ float g_csr_w[MAXT];

__device__ __forceinline__ uint32_t smem_u32(const void* p) {
    uint32_t a;
    asm("{ .reg .u64 t; cvta.to.shared.u64 t, %1; cvt.u32.u64 %0, t; }"
        : "=r"(a) : "l"(p));
    return a;
}

#define LDSM_X4(r, addr) \
    asm volatile("ldmatrix.sync.aligned.m8n8.x4.shared.b16 {%0,%1,%2,%3}, [%4];" \
        : "=r"((r)[0]), "=r"((r)[1]), "=r"((r)[2]), "=r"((r)[3]) : "r"(addr))
#define MMA_BF16(c, a, b) \
    asm volatile("mma.sync.aligned.m16n8k16.row.col.f32.bf16.bf16.f32 " \
        "{%0,%1,%2,%3}, {%4,%5,%6,%7}, {%8,%9}, {%0,%1,%2,%3};" \
        : "+f"((c)[0]), "+f"((c)[1]), "+f"((c)[2]), "+f"((c)[3]) \
        : "r"((a)[0]), "r"((a)[1]), "r"((a)[2]), "r"((a)[3]), \
          "r"((b)[0]), "r"((b)[1]))
#define CPA16(dst, src, sz) \
    asm volatile("cp.async.ca.shared.global [%0], [%1], 16, %2;" \
        :: "r"(dst), "l"(src), "r"(sz))
#define CPA_COMMIT() asm volatile("cp.async.commit_group;")
#define CPA_WAIT(n)  asm volatile("cp.async.wait_group %0;" :: "n"(n))

// Dynamic SMEM (KB=32 chunk):
//  [0,16384)       xf32[128][32]          fp32 staging (single buffer)
//  [16384,28672)   As_hi[2 sub][128][24]  bf16 (single buffer)
//  [28672,40960)   As_lo[2 sub][128][24]
//  [40960,65536)   Bs_hi[2 buf][2 sub][128][24]
//  [65536,90112)   Bs_lo[2 buf][2 sub][128][24]
#define XOFF   0
#define ASH    16384
#define ASL    28672
#define BSH    40960
#define BSL    65536
#define SUBSZ  6144
#define BBUF   12288
#define GEMM_SMEM 90112

// ---------------------------------------------------------------------------
// Kernel 0: split W [256][128] fp32 -> transposed bf16 hi/lo [128][256]
// ---------------------------------------------------------------------------
__global__ void split_w_kernel(const float* __restrict__ W) {
    int i = blockIdx.x * 256 + threadIdx.x;   // 32768
    int n = i >> 8, k = i & 255;
    float v = W[(size_t)k * F_OUT + n];
    __nv_bfloat16 hi = __float2bfloat16(v);
    float lo = v - __bfloat162float(hi);
    g_wt_hi[n * F_IN + k] = hi;
    g_wt_lo[n * F_IN + k] = __float2bfloat16(lo);
}

// ---------------------------------------------------------------------------
// Kernel 1: init all per-node state (one kernel)
// ---------------------------------------------------------------------------
__global__ void init_kernel(int N) {
    int i = blockIdx.x * blockDim.x + threadIdx.x;
    if (i < N) {
        g_denom[i] = 0.f; g_asrc[i] = 0.f; g_adst[i] = 0.f;
        g_deg[i] = 0; g_cursor[i] = 0;
    }
}

// ---------------------------------------------------------------------------
// Kernel 2: degree count (dst half of edge_index only; independent of gemm)
// ---------------------------------------------------------------------------
__global__ void deg_kernel(const int* __restrict__ ei, int E, int N) {
    int id = blockIdx.x * blockDim.x + threadIdx.x;
    if (id >= E + N) return;
    int d = (id < E) ? ei[E + id] : (id - E);
    atomicAdd(&g_deg[d], 1);
}

// ---------------------------------------------------------------------------
// Kernel 3 (profiled): h = x @ W via mma.sync bf16 (2-term split, 3 terms),
// KB=32 chunks, cp.async pipeline: single-buffer XBUF/A, double-buffer B.
// Per chunk: wait cp -> read XBUF to regs -> sync -> STS A + issue cp(ch+1)
// -> sync -> 2x(ldsm + 48 MMA). 16 barriers total (was 32).
// ---------------------------------------------------------------------------
__global__ void __launch_bounds__(256, 2)
gemm_h_kernel(const float* __restrict__ x,
              const float* __restrict__ att_src,
              const float* __restrict__ att_dst, int N) {
    extern __shared__ char sm[];
    const uint32_t base = smem_u32(sm);

    const int tid  = threadIdx.x;
    const int lane = tid & 31;
    const int wid  = tid >> 5;
    const int warpM = wid & 3;
    const int warpN = wid >> 2;
    const int bm = blockIdx.x * 128;

    float acc[2][8][4];
    #pragma unroll
    for (int m = 0; m < 2; m++)
        #pragma unroll
        for (int n = 0; n < 8; n++)
            #pragma unroll
            for (int q = 0; q < 4; q++) acc[m][n][q] = 0.f;

    // ldmatrix lane offsets (row stride 48B within each 16-k sub-tile)
    const uint32_t aoff = (uint32_t)(warpM * 32 + (lane & 15)) * 48u
                        + (uint32_t)(lane >> 4) * 16u;
    const uint32_t boff4 = (uint32_t)(warpN * 64 + (lane & 7) + (lane >> 4) * 8) * 48u
                         + (uint32_t)((lane >> 3) & 1) * 16u;

    // x staging: 4 float4 per thread; rows (tid>>3)+{0,32,64,96}, k col fixed
    const int xrow0 = tid >> 3;
    const int xk    = (tid & 7) * 4;          // 0..28
    const int xsub  = xk >> 4;                // constant per thread
    const int xcol  = xk & 15;
    // B staging: 2 x 16B per thread; rows (tid>>2)+{0,64}, k col fixed
    const int brow0 = tid >> 2;
    const int bk    = (tid & 3) * 8;          // bf16 units: 0,8,16,24
    const int bsub  = bk >> 4;
    const int bcol  = bk & 15;

    const float* xsrc = x + (size_t)xrow0 * F_IN + xk;   // + bm rows below
    const __nv_bfloat16* bsrc_h = g_wt_hi + (size_t)brow0 * F_IN + bk;
    const __nv_bfloat16* bsrc_l = g_wt_lo + (size_t)brow0 * F_IN + bk;

    const uint32_t xdst = base + XOFF + (uint32_t)(xrow0 * 32 + xk) * 4u;
    const uint32_t bdst_h = base + BSH + (uint32_t)(bsub * SUBSZ + brow0 * 48 + bcol * 2);
    const uint32_t bdst_l = base + BSL + (uint32_t)(bsub * SUBSZ + brow0 * 48 + bcol * 2);

    int xok[4];
    #pragma unroll
    for (int i = 0; i < 4; i++)
        xok[i] = (bm + xrow0 + i * 32 < N) ? 16 : 0;

#define ISSUE_CP(kk_, buf_) do {                                               \
    _Pragma("unroll")                                                          \
    for (int i_ = 0; i_ < 4; i_++)                                             \
        CPA16(xdst + (uint32_t)(i_ * 32 * 32 * 4),                             \
              xsrc + (size_t)(bm + i_ * 32) * F_IN + (kk_), xok[i_]);          \
    _Pragma("unroll")                                                          \
    for (int j_ = 0; j_ < 2; j_++) {                                           \
        CPA16(bdst_h + (buf_) * BBUF + (uint32_t)(j_ * 64 * 48),               \
              bsrc_h + (size_t)(j_ * 64) * F_IN + (kk_), 16);                  \
        CPA16(bdst_l + (buf_) * BBUF + (uint32_t)(j_ * 64 * 48),               \
              bsrc_l + (size_t)(j_ * 64) * F_IN + (kk_), 16);                  \
    }                                                                          \
} while (0)

    ISSUE_CP(0, 0);
    CPA_COMMIT();

    for (int ch = 0; ch < 8; ch++) {
        const int buf = ch & 1;
        CPA_WAIT(0);                       // cp(ch) landed

        // Read own XBUF words to regs (before they're overwritten)
        float4 v[4];
        #pragma unroll
        for (int i = 0; i < 4; i++)
            v[i] = *(const float4*)(sm + XOFF + (xrow0 + i * 32) * 128 + xk * 4);

        __syncthreads();                   // all XBUF reads done; mma(ch-1) done

        // Convert to bf16 hi/lo A tiles (single buffer)
        #pragma unroll
        for (int i = 0; i < 4; i++) {
            char* ah = sm + ASH + xsub * SUBSZ + (xrow0 + i * 32) * 48 + xcol * 2;
            char* al = sm + ASL + xsub * SUBSZ + (xrow0 + i * 32) * 48 + xcol * 2;
            __nv_bfloat162 h0 = __floats2bfloat162_rn(v[i].x, v[i].y);
            __nv_bfloat162 h1 = __floats2bfloat162_rn(v[i].z, v[i].w);
            float2 f0 = __bfloat1622float2(h0), f1 = __bfloat1622float2(h1);
            *(uint2*)ah = make_uint2(*(uint32_t*)&h0, *(uint32_t*)&h1);
            __nv_bfloat162 l0 = __floats2bfloat162_rn(v[i].x - f0.x, v[i].y - f0.y);
            __nv_bfloat162 l1 = __floats2bfloat162_rn(v[i].z - f1.x, v[i].w - f1.y);
            *(uint2*)al = make_uint2(*(uint32_t*)&l0, *(uint32_t*)&l1);
        }

        if (ch < 7) {
            ISSUE_CP((ch + 1) * 32, buf ^ 1);
            CPA_COMMIT();
        }
        __syncthreads();                   // A tiles + B[buf] visible

        #pragma unroll
        for (int sub = 0; sub < 2; sub++) {
            const uint32_t asub = (uint32_t)sub * SUBSZ;
            const uint32_t bb_h = base + BSH + buf * BBUF + asub;
            const uint32_t bb_l = base + BSL + buf * BBUF + asub;
            uint32_t ahf[2][4], alf[2][4];
            LDSM_X4(ahf[0], base + ASH + asub + aoff);
            LDSM_X4(ahf[1], base + ASH + asub + aoff + 16u * 48u);
            LDSM_X4(alf[0], base + ASL + asub + aoff);
            LDSM_X4(alf[1], base + ASL + asub + aoff + 16u * 48u);

            #pragma unroll
            for (int ntp = 0; ntp < 4; ntp++) {
                const int n0 = ntp * 2, n1 = ntp * 2 + 1;
                uint32_t bh4[4], bl4[4];
                LDSM_X4(bh4, bb_h + boff4 + (uint32_t)ntp * 768u);
                LDSM_X4(bl4, bb_l + boff4 + (uint32_t)ntp * 768u);
                MMA_BF16(acc[0][n0], ahf[0], bh4);
                MMA_BF16(acc[1][n0], ahf[1], bh4);
                MMA_BF16(acc[0][n1], ahf[0], bh4 + 2);
                MMA_BF16(acc[1][n1], ahf[1], bh4 + 2);
                MMA_BF16(acc[0][n0], ahf[0], bl4);
                MMA_BF16(acc[1][n0], ahf[1], bl4);
                MMA_BF16(acc[0][n1], ahf[0], bl4 + 2);
                MMA_BF16(acc[1][n1], ahf[1], bl4 + 2);
                MMA_BF16(acc[0][n0], alf[0], bh4);
                MMA_BF16(acc[1][n0], alf[1], bh4);
                MMA_BF16(acc[0][n1], alf[0], bh4 + 2);
                MMA_BF16(acc[1][n1], alf[1], bh4 + 2);
            }
        }
    }

    // Epilogue: store h + fused attention dots
    const int r0 = bm + warpM * 32 + (lane >> 2);
    const int cbase = warpN * 64 + (lane & 3) * 2;
    float ps[2][2], pd[2][2];
    #pragma unroll
    for (int mt = 0; mt < 2; mt++)
        ps[mt][0] = ps[mt][1] = pd[mt][0] = pd[mt][1] = 0.f;

    #pragma unroll
    for (int mt = 0; mt < 2; mt++) {
        int ra = r0 + mt * 16, rb = ra + 8;
        #pragma unroll
        for (int nt = 0; nt < 8; nt++) {
            int c = cbase + nt * 8;
            if (ra < N)
                *(float2*)(g_h + (size_t)ra * F_OUT + c) =
                    make_float2(acc[mt][nt][0], acc[mt][nt][1]);
            if (rb < N)
                *(float2*)(g_h + (size_t)rb * F_OUT + c) =
                    make_float2(acc[mt][nt][2], acc[mt][nt][3]);
            float2 sv = *(const float2*)(att_src + c);
            float2 dv = *(const float2*)(att_dst + c);
            ps[mt][0] += acc[mt][nt][0] * sv.x + acc[mt][nt][1] * sv.y;
            ps[mt][1] += acc[mt][nt][2] * sv.x + acc[mt][nt][3] * sv.y;
            pd[mt][0] += acc[mt][nt][0] * dv.x + acc[mt][nt][1] * dv.y;
            pd[mt][1] += acc[mt][nt][2] * dv.x + acc[mt][nt][3] * dv.y;
        }
    }
    #pragma unroll
    for (int mt = 0; mt < 2; mt++) {
        #pragma unroll
        for (int h = 0; h < 2; h++) {
            float s = ps[mt][h], d = pd[mt][h];
            s += __shfl_xor_sync(0xFFFFFFFFu, s, 1);
            s += __shfl_xor_sync(0xFFFFFFFFu, s, 2);
            d += __shfl_xor_sync(0xFFFFFFFFu, d, 1);
            d += __shfl_xor_sync(0xFFFFFFFFu, d, 2);
            int row = r0 + mt * 16 + h * 8;
            if ((lane & 3) == 0 && row < N) {
                atomicAdd(&g_asrc[row], s);
                atomicAdd(&g_adst[row], d);
            }
        }
    }
}

// ---------------------------------------------------------------------------
// two-level exclusive scan of degrees
// ---------------------------------------------------------------------------
__global__ void scan_block_kernel(int N) {
    const int tid = threadIdx.x;
    const int i   = blockIdx.x * 1024 + tid;
    __shared__ int warp_sums[32];
    int v = (i < N) ? g_deg[i] : 0;
    int incl = v;
    #pragma unroll
    for (int o = 1; o < 32; o <<= 1) {
        int t = __shfl_up_sync(0xFFFFFFFFu, incl, o);
        if ((tid & 31) >= o) incl += t;
    }
    if ((tid & 31) == 31) warp_sums[tid >> 5] = incl;
    __syncthreads();
    if (tid < 32) {
        int ws = warp_sums[tid];
        #pragma unroll
        for (int o = 1; o < 32; o <<= 1) {
            int t = __shfl_up_sync(0xFFFFFFFFu, ws, o);
            if (tid >= o) ws += t;
        }
        warp_sums[tid] = ws;
    }
    __syncthreads();
    int warp_prefix = (tid >= 32) ? warp_sums[(tid >> 5) - 1] : 0;
    if (i < N) g_off[i] = warp_prefix + incl - v;
    if (tid == 0) g_bsum[blockIdx.x] = warp_sums[31];
}

__global__ void scan_tops_kernel(int nb) {
    const int tid = threadIdx.x;
    __shared__ int warp_sums[32];
    int v = (tid < nb) ? g_bsum[tid] : 0;
    int incl = v;
    #pragma unroll
    for (int o = 1; o < 32; o <<= 1) {
        int t = __shfl_up_sync(0xFFFFFFFFu, incl, o);
        if ((tid & 31) >= o) incl += t;
    }
    if ((tid & 31) == 31) warp_sums[tid >> 5] = incl;
    __syncthreads();
    if (tid < 32) {
        int ws = warp_sums[tid];
        #pragma unroll
        for (int o = 1; o < 32; o <<= 1) {
            int t = __shfl_up_sync(0xFFFFFFFFu, ws, o);
            if (tid >= o) ws += t;
        }
        warp_sums[tid] = ws;
    }
    __syncthreads();
    int warp_prefix = (tid >= 32) ? warp_sums[(tid >> 5) - 1] : 0;
    if (tid < nb) g_bpre[tid] = warp_prefix + incl - v;
}

// ---------------------------------------------------------------------------
// edge_kernel: single fused edge pass — logits -> exp -> denom + CSR scatter.
// (No max-shift: logits bounded ~|10|, exp safe in fp32.)
// ---------------------------------------------------------------------------
__global__ void edge_kernel(const int* __restrict__ ei, int E, int N) {
    int id = blockIdx.x * blockDim.x + threadIdx.x;
    if (id >= E + N) return;
    int s, d;
    if (id < E) { s = ei[id]; d = ei[E + id]; }
    else        { s = d = id - E; }
    float e = g_asrc[s] + g_adst[d];
    e = e > 0.f ? e : NEG_SLOPE * e;
    float w = __expf(e);
    atomicAdd(&g_denom[d], w);
    int pos = g_off[d] + g_bpre[d >> 10] + atomicAdd(&g_cursor[d], 1);
    g_csr_src[pos] = s;
    g_csr_w[pos]   = w;
}

// ---------------------------------------------------------------------------
// gather: atomic-free. One warp per dst node; lane = 4 features.
// ---------------------------------------------------------------------------
__global__ void gather_kernel(const float* __restrict__ bias,
                              float* __restrict__ out, int N) {
    int gt   = blockIdx.x * blockDim.x + threadIdx.x;
    int node = gt >> 5;
    int lane = gt & 31;
    if (node >= N) return;

    float4 acc = *(const float4*)(bias + lane * 4);
    float dinv = 1.f / (g_denom[node] + EPS_A);
    int off = g_off[node] + g_bpre[node >> 10];
    int deg = g_deg[node];

    for (int i = 0; i < deg; i++) {
        int s   = g_csr_src[off + i];
        float a = g_csr_w[off + i] * dinv;
        float4 hv = *(const float4*)(g_h + (size_t)s * F_OUT + lane * 4);
        acc.x += a * hv.x;
        acc.y += a * hv.y;
        acc.z += a * hv.z;
        acc.w += a * hv.w;
    }
    *(float4*)(out + (size_t)node * F_OUT + lane * 4) = acc;
}

// ---------------------------------------------------------------------------
extern "C" void kernel_launch(void* const* d_in, const int* in_sizes, int n_in,
                              void* d_out, int out_size) {
    const float* x       = (const float*)d_in[0];
    const int*   ei      = (const int*)d_in[1];
    const float* W       = (const float*)d_in[2];
    const float* att_src = (const float*)d_in[3];
    const float* att_dst = (const float*)d_in[4];
    const float* bias    = (const float*)d_in[5];
    float*       out     = (float*)d_out;

    const int Fout = in_sizes[3];            // 128
    const int Fin  = in_sizes[2] / Fout;     // 256
    const int N    = in_sizes[0] / Fin;      // 50000
    const int E    = in_sizes[1] / 2;        // 800000
    const int tot  = E + N;
    const int nb   = (N + 1023) / 1024;

    cudaFuncSetAttribute(gemm_h_kernel,
                         cudaFuncAttributeMaxDynamicSharedMemorySize,
                         GEMM_SMEM);

    split_w_kernel<<<(F_IN * F_OUT) / 256, 256>>>(W);   // launch 0
    init_kernel<<<(N + 255) / 256, 256>>>(N);           // launch 1
    deg_kernel<<<(tot + 255) / 256, 256>>>(ei, E, N);   // launch 2
    gemm_h_kernel<<<(N + 127) / 128, 256, GEMM_SMEM>>>(x, att_src, att_dst, N); // 3 (profiled)
    scan_block_kernel<<<nb, 1024>>>(N);
    scan_tops_kernel<<<1, 1024>>>(nb);
    edge_kernel<<<(tot + 255) / 256, 256>>>(ei, E, N);
    gather_kernel<<<((size_t)N * 32 + 255) / 256, 256>>>(bias, out, N);
}

// round 16
// speedup vs baseline: 1.7153x; 1.0706x over previous
#include <cuda_runtime.h>
#include <cuda_bf16.h>
#include <cuda_fp16.h>
#include <cstdint>

#define F_IN      256
#define F_OUT     128
#define NEG_SLOPE 0.2f
#define EPS_A     1e-16f
#define MAXN      50000
#define MAXE      800000
#define MAXT      (MAXE + MAXN)
#define MAXB      ((MAXN + 1023) / 1024)

// Scratch (device globals: allocation-free kernel_launch)
__device__ __half g_h[(size_t)MAXN * F_OUT];     // 12.8 MB (fp16: 1.4e-4 RMS, safe)
__device__ __nv_bfloat16 g_wt_hi[F_OUT * F_IN];  // W^T hi [128][256]
__device__ __nv_bfloat16 g_wt_lo[F_OUT * F_IN];  // W^T lo
__device__ float g_asrc[MAXN];
__device__ float g_adst[MAXN];
__device__ float g_denom[MAXN];
__device__ int   g_deg[MAXN];
__device__ int   g_off[MAXN];
__device__ int   g_bsum[MAXB];
__device__ int   g_bpre[MAXB];
__device__ int   g_cursor[MAXN];
__device__ int   g_csr_src[MAXT];
__device__ float g_csr_w[MAXT];

__device__ __forceinline__ uint32_t smem_u32(const void* p) {
    uint32_t a;
    asm("{ .reg .u64 t; cvta.to.shared.u64 t, %1; cvt.u32.u64 %0, t; }"
        : "=r"(a) : "l"(p));
    return a;
}

#define LDSM_X4(r, addr) \
    asm volatile("ldmatrix.sync.aligned.m8n8.x4.shared.b16 {%0,%1,%2,%3}, [%4];" \
        : "=r"((r)[0]), "=r"((r)[1]), "=r"((r)[2]), "=r"((r)[3]) : "r"(addr))
#define MMA_BF16(c, a, b) \
    asm volatile("mma.sync.aligned.m16n8k16.row.col.f32.bf16.bf16.f32 " \
        "{%0,%1,%2,%3}, {%4,%5,%6,%7}, {%8,%9}, {%0,%1,%2,%3};" \
        : "+f"((c)[0]), "+f"((c)[1]), "+f"((c)[2]), "+f"((c)[3]) \
        : "r"((a)[0]), "r"((a)[1]), "r"((a)[2]), "r"((a)[3]), \
          "r"((b)[0]), "r"((b)[1]))
#define CPA16(dst, src, sz) \
    asm volatile("cp.async.ca.shared.global [%0], [%1], 16, %2;" \
        :: "r"(dst), "l"(src), "r"(sz))
#define CPA_COMMIT() asm volatile("cp.async.commit_group;")
#define CPA_WAIT(n)  asm volatile("cp.async.wait_group %0;" :: "n"(n))

// Dynamic SMEM (KB=32 chunk): see R15
#define XOFF   0
#define ASH    16384
#define ASL    28672
#define BSH    40960
#define BSL    65536
#define SUBSZ  6144
#define BBUF   12288
#define GEMM_SMEM 90112

// ---------------------------------------------------------------------------
// Kernel 0: fused W split (32768 items) + per-node init (N items)
// ---------------------------------------------------------------------------
__global__ void initsplit_kernel(const float* __restrict__ W, int N) {
    int i = blockIdx.x * blockDim.x + threadIdx.x;
    if (i < N) {
        g_denom[i] = 0.f; g_asrc[i] = 0.f; g_adst[i] = 0.f;
        g_deg[i] = 0; g_cursor[i] = 0;
    }
    if (i < F_IN * F_OUT) {
        int n = i >> 8, k = i & 255;
        float v = W[(size_t)k * F_OUT + n];
        __nv_bfloat16 hi = __float2bfloat16(v);
        float lo = v - __bfloat162float(hi);
        g_wt_hi[n * F_IN + k] = hi;
        g_wt_lo[n * F_IN + k] = __float2bfloat16(lo);
    }
}

// ---------------------------------------------------------------------------
// Kernel 1: degree count (dst half of edge_index only; independent of gemm)
// ---------------------------------------------------------------------------
__global__ void deg_kernel(const int* __restrict__ ei, int E, int N) {
    int id = blockIdx.x * blockDim.x + threadIdx.x;
    if (id >= E + N) return;
    int d = (id < E) ? ei[E + id] : (id - E);
    atomicAdd(&g_deg[d], 1);
}

// ---------------------------------------------------------------------------
// scan_block (launch 2): per-block exclusive scan of degrees
// ---------------------------------------------------------------------------
__global__ void scan_block_kernel(int N) {
    const int tid = threadIdx.x;
    const int i   = blockIdx.x * 1024 + tid;
    __shared__ int warp_sums[32];
    int v = (i < N) ? g_deg[i] : 0;
    int incl = v;
    #pragma unroll
    for (int o = 1; o < 32; o <<= 1) {
        int t = __shfl_up_sync(0xFFFFFFFFu, incl, o);
        if ((tid & 31) >= o) incl += t;
    }
    if ((tid & 31) == 31) warp_sums[tid >> 5] = incl;
    __syncthreads();
    if (tid < 32) {
        int ws = warp_sums[tid];
        #pragma unroll
        for (int o = 1; o < 32; o <<= 1) {
            int t = __shfl_up_sync(0xFFFFFFFFu, ws, o);
            if (tid >= o) ws += t;
        }
        warp_sums[tid] = ws;
    }
    __syncthreads();
    int warp_prefix = (tid >= 32) ? warp_sums[(tid >> 5) - 1] : 0;
    if (i < N) g_off[i] = warp_prefix + incl - v;
    if (tid == 0) g_bsum[blockIdx.x] = warp_sums[31];
}

// ---------------------------------------------------------------------------
// Kernel 3 (profiled): h = x @ W via mma.sync bf16 (2-term split, 3 terms),
// KB=32 chunks, cp.async pipeline; h stored fp16; fused attention dots.
// ---------------------------------------------------------------------------
__global__ void __launch_bounds__(256, 2)
gemm_h_kernel(const float* __restrict__ x,
              const float* __restrict__ att_src,
              const float* __restrict__ att_dst, int N) {
    extern __shared__ char sm[];
    const uint32_t base = smem_u32(sm);

    const int tid  = threadIdx.x;
    const int lane = tid & 31;
    const int wid  = tid >> 5;
    const int warpM = wid & 3;
    const int warpN = wid >> 2;
    const int bm = blockIdx.x * 128;

    float acc[2][8][4];
    #pragma unroll
    for (int m = 0; m < 2; m++)
        #pragma unroll
        for (int n = 0; n < 8; n++)
            #pragma unroll
            for (int q = 0; q < 4; q++) acc[m][n][q] = 0.f;

    const uint32_t aoff = (uint32_t)(warpM * 32 + (lane & 15)) * 48u
                        + (uint32_t)(lane >> 4) * 16u;
    const uint32_t boff4 = (uint32_t)(warpN * 64 + (lane & 7) + (lane >> 4) * 8) * 48u
                         + (uint32_t)((lane >> 3) & 1) * 16u;

    const int xrow0 = tid >> 3;
    const int xk    = (tid & 7) * 4;
    const int xsub  = xk >> 4;
    const int xcol  = xk & 15;
    const int brow0 = tid >> 2;
    const int bk    = (tid & 3) * 8;
    const int bsub  = bk >> 4;
    const int bcol  = bk & 15;

    const float* xsrc = x + (size_t)xrow0 * F_IN + xk;
    const __nv_bfloat16* bsrc_h = g_wt_hi + (size_t)brow0 * F_IN + bk;
    const __nv_bfloat16* bsrc_l = g_wt_lo + (size_t)brow0 * F_IN + bk;

    const uint32_t xdst = base + XOFF + (uint32_t)(xrow0 * 32 + xk) * 4u;
    const uint32_t bdst_h = base + BSH + (uint32_t)(bsub * SUBSZ + brow0 * 48 + bcol * 2);
    const uint32_t bdst_l = base + BSL + (uint32_t)(bsub * SUBSZ + brow0 * 48 + bcol * 2);

    int xok[4];
    #pragma unroll
    for (int i = 0; i < 4; i++)
        xok[i] = (bm + xrow0 + i * 32 < N) ? 16 : 0;

#define ISSUE_CP(kk_, buf_) do {                                               \
    _Pragma("unroll")                                                          \
    for (int i_ = 0; i_ < 4; i_++)                                             \
        CPA16(xdst + (uint32_t)(i_ * 32 * 32 * 4),                             \
              xsrc + (size_t)(bm + i_ * 32) * F_IN + (kk_), xok[i_]);          \
    _Pragma("unroll")                                                          \
    for (int j_ = 0; j_ < 2; j_++) {                                           \
        CPA16(bdst_h + (buf_) * BBUF + (uint32_t)(j_ * 64 * 48),               \
              bsrc_h + (size_t)(j_ * 64) * F_IN + (kk_), 16);                  \
        CPA16(bdst_l + (buf_) * BBUF + (uint32_t)(j_ * 64 * 48),               \
              bsrc_l + (size_t)(j_ * 64) * F_IN + (kk_), 16);                  \
    }                                                                          \
} while (0)

    ISSUE_CP(0, 0);
    CPA_COMMIT();

    for (int ch = 0; ch < 8; ch++) {
        const int buf = ch & 1;
        CPA_WAIT(0);

        float4 v[4];
        #pragma unroll
        for (int i = 0; i < 4; i++)
            v[i] = *(const float4*)(sm + XOFF + (xrow0 + i * 32) * 128 + xk * 4);

        __syncthreads();

        #pragma unroll
        for (int i = 0; i < 4; i++) {
            char* ah = sm + ASH + xsub * SUBSZ + (xrow0 + i * 32) * 48 + xcol * 2;
            char* al = sm + ASL + xsub * SUBSZ + (xrow0 + i * 32) * 48 + xcol * 2;
            __nv_bfloat162 h0 = __floats2bfloat162_rn(v[i].x, v[i].y);
            __nv_bfloat162 h1 = __floats2bfloat162_rn(v[i].z, v[i].w);
            float2 f0 = __bfloat1622float2(h0), f1 = __bfloat1622float2(h1);
            *(uint2*)ah = make_uint2(*(uint32_t*)&h0, *(uint32_t*)&h1);
            __nv_bfloat162 l0 = __floats2bfloat162_rn(v[i].x - f0.x, v[i].y - f0.y);
            __nv_bfloat162 l1 = __floats2bfloat162_rn(v[i].z - f1.x, v[i].w - f1.y);
            *(uint2*)al = make_uint2(*(uint32_t*)&l0, *(uint32_t*)&l1);
        }

        if (ch < 7) {
            ISSUE_CP((ch + 1) * 32, buf ^ 1);
            CPA_COMMIT();
        }
        __syncthreads();

        #pragma unroll
        for (int sub = 0; sub < 2; sub++) {
            const uint32_t asub = (uint32_t)sub * SUBSZ;
            const uint32_t bb_h = base + BSH + buf * BBUF + asub;
            const uint32_t bb_l = base + BSL + buf * BBUF + asub;
            uint32_t ahf[2][4], alf[2][4];
            LDSM_X4(ahf[0], base + ASH + asub + aoff);
            LDSM_X4(ahf[1], base + ASH + asub + aoff + 16u * 48u);
            LDSM_X4(alf[0], base + ASL + asub + aoff);
            LDSM_X4(alf[1], base + ASL + asub + aoff + 16u * 48u);

            #pragma unroll
            for (int ntp = 0; ntp < 4; ntp++) {
                const int n0 = ntp * 2, n1 = ntp * 2 + 1;
                uint32_t bh4[4], bl4[4];
                LDSM_X4(bh4, bb_h + boff4 + (uint32_t)ntp * 768u);
                LDSM_X4(bl4, bb_l + boff4 + (uint32_t)ntp * 768u);
                MMA_BF16(acc[0][n0], ahf[0], bh4);
                MMA_BF16(acc[1][n0], ahf[1], bh4);
                MMA_BF16(acc[0][n1], ahf[0], bh4 + 2);
                MMA_BF16(acc[1][n1], ahf[1], bh4 + 2);
                MMA_BF16(acc[0][n0], ahf[0], bl4);
                MMA_BF16(acc[1][n0], ahf[1], bl4);
                MMA_BF16(acc[0][n1], ahf[0], bl4 + 2);
                MMA_BF16(acc[1][n1], ahf[1], bl4 + 2);
                MMA_BF16(acc[0][n0], alf[0], bh4);
                MMA_BF16(acc[1][n0], alf[1], bh4);
                MMA_BF16(acc[0][n1], alf[0], bh4 + 2);
                MMA_BF16(acc[1][n1], alf[1], bh4 + 2);
            }
        }
    }

    // Epilogue: store h (fp16) + fused attention dots (fp32 from acc)
    const int r0 = bm + warpM * 32 + (lane >> 2);
    const int cbase = warpN * 64 + (lane & 3) * 2;
    float ps[2][2], pd[2][2];
    #pragma unroll
    for (int mt = 0; mt < 2; mt++)
        ps[mt][0] = ps[mt][1] = pd[mt][0] = pd[mt][1] = 0.f;

    #pragma unroll
    for (int mt = 0; mt < 2; mt++) {
        int ra = r0 + mt * 16, rb = ra + 8;
        #pragma unroll
        for (int nt = 0; nt < 8; nt++) {
            int c = cbase + nt * 8;
            if (ra < N)
                *(__half2*)(g_h + (size_t)ra * F_OUT + c) =
                    __floats2half2_rn(acc[mt][nt][0], acc[mt][nt][1]);
            if (rb < N)
                *(__half2*)(g_h + (size_t)rb * F_OUT + c) =
                    __floats2half2_rn(acc[mt][nt][2], acc[mt][nt][3]);
            float2 sv = *(const float2*)(att_src + c);
            float2 dv = *(const float2*)(att_dst + c);
            ps[mt][0] += acc[mt][nt][0] * sv.x + acc[mt][nt][1] * sv.y;
            ps[mt][1] += acc[mt][nt][2] * sv.x + acc[mt][nt][3] * sv.y;
            pd[mt][0] += acc[mt][nt][0] * dv.x + acc[mt][nt][1] * dv.y;
            pd[mt][1] += acc[mt][nt][2] * dv.x + acc[mt][nt][3] * dv.y;
        }
    }
    #pragma unroll
    for (int mt = 0; mt < 2; mt++) {
        #pragma unroll
        for (int h = 0; h < 2; h++) {
            float s = ps[mt][h], d = pd[mt][h];
            s += __shfl_xor_sync(0xFFFFFFFFu, s, 1);
            s += __shfl_xor_sync(0xFFFFFFFFu, s, 2);
            d += __shfl_xor_sync(0xFFFFFFFFu, d, 1);
            d += __shfl_xor_sync(0xFFFFFFFFu, d, 2);
            int row = r0 + mt * 16 + h * 8;
            if ((lane & 3) == 0 && row < N) {
                atomicAdd(&g_asrc[row], s);
                atomicAdd(&g_adst[row], d);
            }
        }
    }
}

// ---------------------------------------------------------------------------
// scan_tops: exclusive scan of block totals
// ---------------------------------------------------------------------------
__global__ void scan_tops_kernel(int nb) {
    const int tid = threadIdx.x;
    __shared__ int warp_sums[32];
    int v = (tid < nb) ? g_bsum[tid] : 0;
    int incl = v;
    #pragma unroll
    for (int o = 1; o < 32; o <<= 1) {
        int t = __shfl_up_sync(0xFFFFFFFFu, incl, o);
        if ((tid & 31) >= o) incl += t;
    }
    if ((tid & 31) == 31) warp_sums[tid >> 5] = incl;
    __syncthreads();
    if (tid < 32) {
        int ws = warp_sums[tid];
        #pragma unroll
        for (int o = 1; o < 32; o <<= 1) {
            int t = __shfl_up_sync(0xFFFFFFFFu, ws, o);
            if (tid >= o) ws += t;
        }
        warp_sums[tid] = ws;
    }
    __syncthreads();
    int warp_prefix = (tid >= 32) ? warp_sums[(tid >> 5) - 1] : 0;
    if (tid < nb) g_bpre[tid] = warp_prefix + incl - v;
}

// ---------------------------------------------------------------------------
// edge_kernel: single fused edge pass — logits -> exp -> denom + CSR scatter.
// ---------------------------------------------------------------------------
__global__ void edge_kernel(const int* __restrict__ ei, int E, int N) {
    int id = blockIdx.x * blockDim.x + threadIdx.x;
    if (id >= E + N) return;
    int s, d;
    if (id < E) { s = ei[id]; d = ei[E + id]; }
    else        { s = d = id - E; }
    float e = g_asrc[s] + g_adst[d];
    e = e > 0.f ? e : NEG_SLOPE * e;
    float w = __expf(e);
    atomicAdd(&g_denom[d], w);
    int pos = g_off[d] + g_bpre[d >> 10] + atomicAdd(&g_cursor[d], 1);
    g_csr_src[pos] = s;
    g_csr_w[pos]   = w;
}

// ---------------------------------------------------------------------------
// gather: atomic-free; fp16 h rows (256B/row), fp32 accumulate.
// ---------------------------------------------------------------------------
__global__ void gather_kernel(const float* __restrict__ bias,
                              float* __restrict__ out, int N) {
    int gt   = blockIdx.x * blockDim.x + threadIdx.x;
    int node = gt >> 5;
    int lane = gt & 31;
    if (node >= N) return;

    float4 acc = *(const float4*)(bias + lane * 4);
    float dinv = 1.f / (g_denom[node] + EPS_A);
    int off = g_off[node] + g_bpre[node >> 10];
    int deg = g_deg[node];

    for (int i = 0; i < deg; i++) {
        int s   = g_csr_src[off + i];
        float a = g_csr_w[off + i] * dinv;
        uint2 hv = *(const uint2*)(g_h + (size_t)s * F_OUT + lane * 4);
        float2 f0 = __half22float2(*(__half2*)&hv.x);
        float2 f1 = __half22float2(*(__half2*)&hv.y);
        acc.x += a * f0.x;
        acc.y += a * f0.y;
        acc.z += a * f1.x;
        acc.w += a * f1.y;
    }
    *(float4*)(out + (size_t)node * F_OUT + lane * 4) = acc;
}

// ---------------------------------------------------------------------------
extern "C" void kernel_launch(void* const* d_in, const int* in_sizes, int n_in,
                              void* d_out, int out_size) {
    const float* x       = (const float*)d_in[0];
    const int*   ei      = (const int*)d_in[1];
    const float* W       = (const float*)d_in[2];
    const float* att_src = (const float*)d_in[3];
    const float* att_dst = (const float*)d_in[4];
    const float* bias    = (const float*)d_in[5];
    float*       out     = (float*)d_out;

    const int Fout = in_sizes[3];            // 128
    const int Fin  = in_sizes[2] / Fout;     // 256
    const int N    = in_sizes[0] / Fin;      // 50000
    const int E    = in_sizes[1] / 2;        // 800000
    const int tot  = E + N;
    const int nb   = (N + 1023) / 1024;
    const int isn  = (N > F_IN * F_OUT) ? N : F_IN * F_OUT;

    cudaFuncSetAttribute(gemm_h_kernel,
                         cudaFuncAttributeMaxDynamicSharedMemorySize,
                         GEMM_SMEM);

    initsplit_kernel<<<(isn + 255) / 256, 256>>>(W, N);  // launch 0
    deg_kernel<<<(tot + 255) / 256, 256>>>(ei, E, N);    // launch 1
    scan_block_kernel<<<nb, 1024>>>(N);                  // launch 2
    gemm_h_kernel<<<(N + 127) / 128, 256, GEMM_SMEM>>>(x, att_src, att_dst, N); // 3 (profiled)
    scan_tops_kernel<<<1, 1024>>>(nb);
    edge_kernel<<<(tot + 255) / 256, 256>>>(ei, E, N);
    gather_kernel<<<((size_t)N * 32 + 255) / 256, 256>>>(bias, out, N);
}

// round 17
// speedup vs baseline: 1.7320x; 1.0097x over previous
#include <cuda_runtime.h>
#include <cuda_bf16.h>
#include <cuda_fp16.h>
#include <cstdint>

#define F_IN      256
#define F_OUT     128
#define NEG_SLOPE 0.2f
#define EPS_A     1e-16f
#define MAXN      50000
#define MAXE      800000
#define MAXT      (MAXE + MAXN)
#define MAXB      ((MAXN + 1023) / 1024)

// Scratch (device globals: allocation-free kernel_launch)
__device__ __half g_h[(size_t)MAXN * F_OUT];     // 12.8 MB
__device__ __nv_bfloat16 g_wt_hi[F_OUT * F_IN];  // W^T hi [128][256]
__device__ __nv_bfloat16 g_wt_lo[F_OUT * F_IN];  // W^T lo
__device__ float g_asrc[MAXN];
__device__ float g_adst[MAXN];
__device__ int   g_deg[MAXN];
__device__ int   g_off[MAXN];
__device__ int   g_bsum[MAXB];
__device__ int   g_bpre[MAXB];
__device__ int   g_cursor[MAXN];
__device__ int2  g_csr[MAXT];                    // (src, w bits)

__device__ __forceinline__ uint32_t smem_u32(const void* p) {
    uint32_t a;
    asm("{ .reg .u64 t; cvta.to.shared.u64 t, %1; cvt.u32.u64 %0, t; }"
        : "=r"(a) : "l"(p));
    return a;
}

#define LDSM_X4(r, addr) \
    asm volatile("ldmatrix.sync.aligned.m8n8.x4.shared.b16 {%0,%1,%2,%3}, [%4];" \
        : "=r"((r)[0]), "=r"((r)[1]), "=r"((r)[2]), "=r"((r)[3]) : "r"(addr))
#define MMA_BF16(c, a, b) \
    asm volatile("mma.sync.aligned.m16n8k16.row.col.f32.bf16.bf16.f32 " \
        "{%0,%1,%2,%3}, {%4,%5,%6,%7}, {%8,%9}, {%0,%1,%2,%3};" \
        : "+f"((c)[0]), "+f"((c)[1]), "+f"((c)[2]), "+f"((c)[3]) \
        : "r"((a)[0]), "r"((a)[1]), "r"((a)[2]), "r"((a)[3]), \
          "r"((b)[0]), "r"((b)[1]))
#define CPA16(dst, src, sz) \
    asm volatile("cp.async.ca.shared.global [%0], [%1], 16, %2;" \
        :: "r"(dst), "l"(src), "r"(sz))
#define CPA_COMMIT() asm volatile("cp.async.commit_group;")
#define CPA_WAIT(n)  asm volatile("cp.async.wait_group %0;" :: "n"(n))

// Dynamic SMEM (KB=32 chunk): see R15
#define XOFF   0
#define ASH    16384
#define ASL    28672
#define BSH    40960
#define BSL    65536
#define SUBSZ  6144
#define BBUF   12288
#define GEMM_SMEM 90112

// ---------------------------------------------------------------------------
// Kernel 0: fused W split (32768 items) + per-node init (N items)
// ---------------------------------------------------------------------------
__global__ void initsplit_kernel(const float* __restrict__ W, int N) {
    int i = blockIdx.x * blockDim.x + threadIdx.x;
    if (i < N) {
        g_asrc[i] = 0.f; g_adst[i] = 0.f;
        g_deg[i] = 0; g_cursor[i] = 0;
    }
    if (i < F_IN * F_OUT) {
        int n = i >> 8, k = i & 255;
        float v = W[(size_t)k * F_OUT + n];
        __nv_bfloat16 hi = __float2bfloat16(v);
        float lo = v - __bfloat162float(hi);
        g_wt_hi[n * F_IN + k] = hi;
        g_wt_lo[n * F_IN + k] = __float2bfloat16(lo);
    }
}

// ---------------------------------------------------------------------------
// Kernel 1: degree count
// ---------------------------------------------------------------------------
__global__ void deg_kernel(const int* __restrict__ ei, int E, int N) {
    int id = blockIdx.x * blockDim.x + threadIdx.x;
    if (id >= E + N) return;
    int d = (id < E) ? ei[E + id] : (id - E);
    atomicAdd(&g_deg[d], 1);
}

// ---------------------------------------------------------------------------
// Kernel 2: per-block exclusive scan of degrees
// ---------------------------------------------------------------------------
__global__ void scan_block_kernel(int N) {
    const int tid = threadIdx.x;
    const int i   = blockIdx.x * 1024 + tid;
    __shared__ int warp_sums[32];
    int v = (i < N) ? g_deg[i] : 0;
    int incl = v;
    #pragma unroll
    for (int o = 1; o < 32; o <<= 1) {
        int t = __shfl_up_sync(0xFFFFFFFFu, incl, o);
        if ((tid & 31) >= o) incl += t;
    }
    if ((tid & 31) == 31) warp_sums[tid >> 5] = incl;
    __syncthreads();
    if (tid < 32) {
        int ws = warp_sums[tid];
        #pragma unroll
        for (int o = 1; o < 32; o <<= 1) {
            int t = __shfl_up_sync(0xFFFFFFFFu, ws, o);
            if (tid >= o) ws += t;
        }
        warp_sums[tid] = ws;
    }
    __syncthreads();
    int warp_prefix = (tid >= 32) ? warp_sums[(tid >> 5) - 1] : 0;
    if (i < N) g_off[i] = warp_prefix + incl - v;
    if (tid == 0) g_bsum[blockIdx.x] = warp_sums[31];
}

// ---------------------------------------------------------------------------
// Kernel 3 (profiled): h = x @ W via mma.sync bf16 (2-term split, 3 terms),
// KB=32 chunks, cp.async pipeline; h stored fp16; fused attention dots.
// ---------------------------------------------------------------------------
__global__ void __launch_bounds__(256, 2)
gemm_h_kernel(const float* __restrict__ x,
              const float* __restrict__ att_src,
              const float* __restrict__ att_dst, int N) {
    extern __shared__ char sm[];
    const uint32_t base = smem_u32(sm);

    const int tid  = threadIdx.x;
    const int lane = tid & 31;
    const int wid  = tid >> 5;
    const int warpM = wid & 3;
    const int warpN = wid >> 2;
    const int bm = blockIdx.x * 128;

    float acc[2][8][4];
    #pragma unroll
    for (int m = 0; m < 2; m++)
        #pragma unroll
        for (int n = 0; n < 8; n++)
            #pragma unroll
            for (int q = 0; q < 4; q++) acc[m][n][q] = 0.f;

    const uint32_t aoff = (uint32_t)(warpM * 32 + (lane & 15)) * 48u
                        + (uint32_t)(lane >> 4) * 16u;
    const uint32_t boff4 = (uint32_t)(warpN * 64 + (lane & 7) + (lane >> 4) * 8) * 48u
                         + (uint32_t)((lane >> 3) & 1) * 16u;

    const int xrow0 = tid >> 3;
    const int xk    = (tid & 7) * 4;
    const int xsub  = xk >> 4;
    const int xcol  = xk & 15;
    const int brow0 = tid >> 2;
    const int bk    = (tid & 3) * 8;
    const int bsub  = bk >> 4;
    const int bcol  = bk & 15;

    const float* xsrc = x + (size_t)xrow0 * F_IN + xk;
    const __nv_bfloat16* bsrc_h = g_wt_hi + (size_t)brow0 * F_IN + bk;
    const __nv_bfloat16* bsrc_l = g_wt_lo + (size_t)brow0 * F_IN + bk;

    const uint32_t xdst = base + XOFF + (uint32_t)(xrow0 * 32 + xk) * 4u;
    const uint32_t bdst_h = base + BSH + (uint32_t)(bsub * SUBSZ + brow0 * 48 + bcol * 2);
    const uint32_t bdst_l = base + BSL + (uint32_t)(bsub * SUBSZ + brow0 * 48 + bcol * 2);

    int xok[4];
    #pragma unroll
    for (int i = 0; i < 4; i++)
        xok[i] = (bm + xrow0 + i * 32 < N) ? 16 : 0;

#define ISSUE_CP(kk_, buf_) do {                                               \
    _Pragma("unroll")                                                          \
    for (int i_ = 0; i_ < 4; i_++)                                             \
        CPA16(xdst + (uint32_t)(i_ * 32 * 32 * 4),                             \
              xsrc + (size_t)(bm + i_ * 32) * F_IN + (kk_), xok[i_]);          \
    _Pragma("unroll")                                                          \
    for (int j_ = 0; j_ < 2; j_++) {                                           \
        CPA16(bdst_h + (buf_) * BBUF + (uint32_t)(j_ * 64 * 48),               \
              bsrc_h + (size_t)(j_ * 64) * F_IN + (kk_), 16);                  \
        CPA16(bdst_l + (buf_) * BBUF + (uint32_t)(j_ * 64 * 48),               \
              bsrc_l + (size_t)(j_ * 64) * F_IN + (kk_), 16);                  \
    }                                                                          \
} while (0)

    ISSUE_CP(0, 0);
    CPA_COMMIT();

    for (int ch = 0; ch < 8; ch++) {
        const int buf = ch & 1;
        CPA_WAIT(0);

        float4 v[4];
        #pragma unroll
        for (int i = 0; i < 4; i++)
            v[i] = *(const float4*)(sm + XOFF + (xrow0 + i * 32) * 128 + xk * 4);

        __syncthreads();

        #pragma unroll
        for (int i = 0; i < 4; i++) {
            char* ah = sm + ASH + xsub * SUBSZ + (xrow0 + i * 32) * 48 + xcol * 2;
            char* al = sm + ASL + xsub * SUBSZ + (xrow0 + i * 32) * 48 + xcol * 2;
            __nv_bfloat162 h0 = __floats2bfloat162_rn(v[i].x, v[i].y);
            __nv_bfloat162 h1 = __floats2bfloat162_rn(v[i].z, v[i].w);
            float2 f0 = __bfloat1622float2(h0), f1 = __bfloat1622float2(h1);
            *(uint2*)ah = make_uint2(*(uint32_t*)&h0, *(uint32_t*)&h1);
            __nv_bfloat162 l0 = __floats2bfloat162_rn(v[i].x - f0.x, v[i].y - f0.y);
            __nv_bfloat162 l1 = __floats2bfloat162_rn(v[i].z - f1.x, v[i].w - f1.y);
            *(uint2*)al = make_uint2(*(uint32_t*)&l0, *(uint32_t*)&l1);
        }

        if (ch < 7) {
            ISSUE_CP((ch + 1) * 32, buf ^ 1);
            CPA_COMMIT();
        }
        __syncthreads();

        #pragma unroll
        for (int sub = 0; sub < 2; sub++) {
            const uint32_t asub = (uint32_t)sub * SUBSZ;
            const uint32_t bb_h = base + BSH + buf * BBUF + asub;
            const uint32_t bb_l = base + BSL + buf * BBUF + asub;
            uint32_t ahf[2][4], alf[2][4];
            LDSM_X4(ahf[0], base + ASH + asub + aoff);
            LDSM_X4(ahf[1], base + ASH + asub + aoff + 16u * 48u);
            LDSM_X4(alf[0], base + ASL + asub + aoff);
            LDSM_X4(alf[1], base + ASL + asub + aoff + 16u * 48u);

            #pragma unroll
            for (int ntp = 0; ntp < 4; ntp++) {
                const int n0 = ntp * 2, n1 = ntp * 2 + 1;
                uint32_t bh4[4], bl4[4];
                LDSM_X4(bh4, bb_h + boff4 + (uint32_t)ntp * 768u);
                LDSM_X4(bl4, bb_l + boff4 + (uint32_t)ntp * 768u);
                MMA_BF16(acc[0][n0], ahf[0], bh4);
                MMA_BF16(acc[1][n0], ahf[1], bh4);
                MMA_BF16(acc[0][n1], ahf[0], bh4 + 2);
                MMA_BF16(acc[1][n1], ahf[1], bh4 + 2);
                MMA_BF16(acc[0][n0], ahf[0], bl4);
                MMA_BF16(acc[1][n0], ahf[1], bl4);
                MMA_BF16(acc[0][n1], ahf[0], bl4 + 2);
                MMA_BF16(acc[1][n1], ahf[1], bl4 + 2);
                MMA_BF16(acc[0][n0], alf[0], bh4);
                MMA_BF16(acc[1][n0], alf[1], bh4);
                MMA_BF16(acc[0][n1], alf[0], bh4 + 2);
                MMA_BF16(acc[1][n1], alf[1], bh4 + 2);
            }
        }
    }

    // Epilogue: store h (fp16) + fused attention dots (fp32 from acc)
    const int r0 = bm + warpM * 32 + (lane >> 2);
    const int cbase = warpN * 64 + (lane & 3) * 2;
    float ps[2][2], pd[2][2];
    #pragma unroll
    for (int mt = 0; mt < 2; mt++)
        ps[mt][0] = ps[mt][1] = pd[mt][0] = pd[mt][1] = 0.f;

    #pragma unroll
    for (int mt = 0; mt < 2; mt++) {
        int ra = r0 + mt * 16, rb = ra + 8;
        #pragma unroll
        for (int nt = 0; nt < 8; nt++) {
            int c = cbase + nt * 8;
            if (ra < N)
                *(__half2*)(g_h + (size_t)ra * F_OUT + c) =
                    __floats2half2_rn(acc[mt][nt][0], acc[mt][nt][1]);
            if (rb < N)
                *(__half2*)(g_h + (size_t)rb * F_OUT + c) =
                    __floats2half2_rn(acc[mt][nt][2], acc[mt][nt][3]);
            float2 sv = *(const float2*)(att_src + c);
            float2 dv = *(const float2*)(att_dst + c);
            ps[mt][0] += acc[mt][nt][0] * sv.x + acc[mt][nt][1] * sv.y;
            ps[mt][1] += acc[mt][nt][2] * sv.x + acc[mt][nt][3] * sv.y;
            pd[mt][0] += acc[mt][nt][0] * dv.x + acc[mt][nt][1] * dv.y;
            pd[mt][1] += acc[mt][nt][2] * dv.x + acc[mt][nt][3] * dv.y;
        }
    }
    #pragma unroll
    for (int mt = 0; mt < 2; mt++) {
        #pragma unroll
        for (int h = 0; h < 2; h++) {
            float s = ps[mt][h], d = pd[mt][h];
            s += __shfl_xor_sync(0xFFFFFFFFu, s, 1);
            s += __shfl_xor_sync(0xFFFFFFFFu, s, 2);
            d += __shfl_xor_sync(0xFFFFFFFFu, d, 1);
            d += __shfl_xor_sync(0xFFFFFFFFu, d, 2);
            int row = r0 + mt * 16 + h * 8;
            if ((lane & 3) == 0 && row < N) {
                atomicAdd(&g_asrc[row], s);
                atomicAdd(&g_adst[row], d);
            }
        }
    }
}

// ---------------------------------------------------------------------------
// scan_tops: exclusive scan of block totals
// ---------------------------------------------------------------------------
__global__ void scan_tops_kernel(int nb) {
    const int tid = threadIdx.x;
    __shared__ int warp_sums[32];
    int v = (tid < nb) ? g_bsum[tid] : 0;
    int incl = v;
    #pragma unroll
    for (int o = 1; o < 32; o <<= 1) {
        int t = __shfl_up_sync(0xFFFFFFFFu, incl, o);
        if ((tid & 31) >= o) incl += t;
    }
    if ((tid & 31) == 31) warp_sums[tid >> 5] = incl;
    __syncthreads();
    if (tid < 32) {
        int ws = warp_sums[tid];
        #pragma unroll
        for (int o = 1; o < 32; o <<= 1) {
            int t = __shfl_up_sync(0xFFFFFFFFu, ws, o);
            if (tid >= o) ws += t;
        }
        warp_sums[tid] = ws;
    }
    __syncthreads();
    int warp_prefix = (tid >= 32) ? warp_sums[(tid >> 5) - 1] : 0;
    if (tid < nb) g_bpre[tid] = warp_prefix + incl - v;
}

// ---------------------------------------------------------------------------
// edge_kernel: logits -> exp -> packed CSR scatter (no denom atomic:
// denom = segment sum of w, computed for free in the gather)
// ---------------------------------------------------------------------------
__global__ void edge_kernel(const int* __restrict__ ei, int E, int N) {
    int id = blockIdx.x * blockDim.x + threadIdx.x;
    if (id >= E + N) return;
    int s, d;
    if (id < E) { s = ei[id]; d = ei[E + id]; }
    else        { s = d = id - E; }
    float e = g_asrc[s] + g_adst[d];
    e = e > 0.f ? e : NEG_SLOPE * e;
    float w = __expf(e);
    int pos = g_off[d] + g_bpre[d >> 10] + atomicAdd(&g_cursor[d], 1);
    g_csr[pos] = make_int2(s, __float_as_int(w));
}

// ---------------------------------------------------------------------------
// gather: atomic-free; fp16 h; unroll-2 with independent accumulators;
// denom computed inline as wsum (broadcast scalar).
// ---------------------------------------------------------------------------
__global__ void gather_kernel(const float* __restrict__ bias,
                              float* __restrict__ out, int N) {
    int gt   = blockIdx.x * blockDim.x + threadIdx.x;
    int node = gt >> 5;
    int lane = gt & 31;
    if (node >= N) return;

    float4 acc0 = make_float4(0.f, 0.f, 0.f, 0.f);
    float4 acc1 = make_float4(0.f, 0.f, 0.f, 0.f);
    float wsum = 0.f;
    int off = g_off[node] + g_bpre[node >> 10];
    int deg = g_deg[node];

    int i = 0;
    for (; i + 2 <= deg; i += 2) {
        int2 cw0 = g_csr[off + i];
        int2 cw1 = g_csr[off + i + 1];
        float w0 = __int_as_float(cw0.y);
        float w1 = __int_as_float(cw1.y);
        uint2 hv0 = *(const uint2*)(g_h + (size_t)cw0.x * F_OUT + lane * 4);
        uint2 hv1 = *(const uint2*)(g_h + (size_t)cw1.x * F_OUT + lane * 4);
        wsum += w0 + w1;
        float2 a0 = __half22float2(*(__half2*)&hv0.x);
        float2 b0 = __half22float2(*(__half2*)&hv0.y);
        float2 a1 = __half22float2(*(__half2*)&hv1.x);
        float2 b1 = __half22float2(*(__half2*)&hv1.y);
        acc0.x += w0 * a0.x; acc0.y += w0 * a0.y;
        acc0.z += w0 * b0.x; acc0.w += w0 * b0.y;
        acc1.x += w1 * a1.x; acc1.y += w1 * a1.y;
        acc1.z += w1 * b1.x; acc1.w += w1 * b1.y;
    }
    if (i < deg) {
        int2 cw = g_csr[off + i];
        float w = __int_as_float(cw.y);
        uint2 hv = *(const uint2*)(g_h + (size_t)cw.x * F_OUT + lane * 4);
        wsum += w;
        float2 a = __half22float2(*(__half2*)&hv.x);
        float2 b = __half22float2(*(__half2*)&hv.y);
        acc0.x += w * a.x; acc0.y += w * a.y;
        acc0.z += w * b.x; acc0.w += w * b.y;
    }

    float dinv = 1.f / (wsum + EPS_A);
    float4 bv = *(const float4*)(bias + lane * 4);
    float4 o;
    o.x = bv.x + (acc0.x + acc1.x) * dinv;
    o.y = bv.y + (acc0.y + acc1.y) * dinv;
    o.z = bv.z + (acc0.z + acc1.z) * dinv;
    o.w = bv.w + (acc0.w + acc1.w) * dinv;
    *(float4*)(out + (size_t)node * F_OUT + lane * 4) = o;
}

// ---------------------------------------------------------------------------
extern "C" void kernel_launch(void* const* d_in, const int* in_sizes, int n_in,
                              void* d_out, int out_size) {
    const float* x       = (const float*)d_in[0];
    const int*   ei      = (const int*)d_in[1];
    const float* W       = (const float*)d_in[2];
    const float* att_src = (const float*)d_in[3];
    const float* att_dst = (const float*)d_in[4];
    const float* bias    = (const float*)d_in[5];
    float*       out     = (float*)d_out;

    const int Fout = in_sizes[3];            // 128
    const int Fin  = in_sizes[2] / Fout;     // 256
    const int N    = in_sizes[0] / Fin;      // 50000
    const int E    = in_sizes[1] / 2;        // 800000
    const int tot  = E + N;
    const int nb   = (N + 1023) / 1024;
    const int isn  = (N > F_IN * F_OUT) ? N : F_IN * F_OUT;

    cudaFuncSetAttribute(gemm_h_kernel,
                         cudaFuncAttributeMaxDynamicSharedMemorySize,
                         GEMM_SMEM);

    initsplit_kernel<<<(isn + 255) / 256, 256>>>(W, N);  // launch 0
    deg_kernel<<<(tot + 255) / 256, 256>>>(ei, E, N);    // launch 1
    scan_block_kernel<<<nb, 1024>>>(N);                  // launch 2
    gemm_h_kernel<<<(N + 127) / 128, 256, GEMM_SMEM>>>(x, att_src, att_dst, N); // 3 (profiled)
    scan_tops_kernel<<<1, 1024>>>(nb);
    edge_kernel<<<(tot + 255) / 256, 256>>>(ei, E, N);
    gather_kernel<<<((size_t)N * 32 + 255) / 256, 256>>>(bias, out, N);
}